// round 1
// baseline (speedup 1.0000x reference)
#include <cuda_runtime.h>
#include <cstdint>

#define N_NODES 100000
#define E_MAX   1600000
#define IN_F    512
#define HID     128
#define NCLS    32

// ---------------- scratch (device globals; no allocation allowed) ------------
__device__ int   g_cnt[N_NODES];        // #edges with dst=i (excl. self loop)
__device__ int   g_rowstart[N_NODES];   // CSR row start (exclusive scan of cnt)
__device__ int   g_cursor[N_NODES];     // fill cursors
__device__ float g_dinv[N_NODES];       // 1/sqrt(deg), deg = cnt+1 (self loop)
__device__ int   g_col[E_MAX];          // CSR column (src) indices
__device__ float g_h1[(size_t)N_NODES * HID];   // x @ W1
__device__ float g_a1[(size_t)N_NODES * HID];   // relu(agg1 + b1)
__device__ float g_h2[(size_t)N_NODES * NCLS];  // a1 @ W2
__device__ int   g_blocksums[128];

// ---------------- small helpers ------------------------------------------
__global__ void k_zero_cnt() {
    int i = blockIdx.x * blockDim.x + threadIdx.x;
    if (i < N_NODES) g_cnt[i] = 0;
}

__global__ void k_hist(const int* __restrict__ dst, int E) {
    int e = blockIdx.x * blockDim.x + threadIdx.x;
    if (e < E) atomicAdd(&g_cnt[dst[e]], 1);
}

// scan stage 1: each block scans 1024 elements, writes per-element EXCLUSIVE
// (local) prefix into g_rowstart and block total into g_blocksums.
__global__ void k_scan1() {
    __shared__ int sh[256];
    int b = blockIdx.x, t = threadIdx.x;
    int base = b * 1024 + t * 4;
    int v[4];
    int local = 0;
#pragma unroll
    for (int q = 0; q < 4; q++) {
        int i = base + q;
        v[q] = (i < N_NODES) ? g_cnt[i] : 0;
        local += v[q];
    }
    sh[t] = local;
    __syncthreads();
#pragma unroll
    for (int off = 1; off < 256; off <<= 1) {
        int add = (t >= off) ? sh[t - off] : 0;
        __syncthreads();
        sh[t] += add;
        __syncthreads();
    }
    int run = sh[t] - local;   // exclusive prefix of this thread's 4 elems
    if (t == 255) g_blocksums[b] = sh[255];
#pragma unroll
    for (int q = 0; q < 4; q++) {
        int i = base + q;
        if (i < N_NODES) g_rowstart[i] = run;
        run += v[q];
    }
}

// scan stage 2: exclusive scan of block sums (nblk <= 128), single block.
__global__ void k_scan2(int nblk) {
    __shared__ int sh[128];
    int t = threadIdx.x;
    int v = (t < nblk) ? g_blocksums[t] : 0;
    sh[t] = v;
    __syncthreads();
#pragma unroll
    for (int off = 1; off < 128; off <<= 1) {
        int add = (t >= off) ? sh[t - off] : 0;
        __syncthreads();
        sh[t] += add;
        __syncthreads();
    }
    if (t < nblk) g_blocksums[t] = sh[t] - v;   // exclusive
}

// scan stage 3: add block offsets; init cursors; compute dinv.
__global__ void k_scan3() {
    int i = blockIdx.x * blockDim.x + threadIdx.x;
    if (i >= N_NODES) return;
    int rs = g_rowstart[i] + g_blocksums[i >> 10];
    g_rowstart[i] = rs;
    g_cursor[i]   = rs;
    g_dinv[i]     = rsqrtf((float)(g_cnt[i] + 1));   // +1 = self loop
}

__global__ void k_fill(const int* __restrict__ src, const int* __restrict__ dst, int E) {
    int e = blockIdx.x * blockDim.x + threadIdx.x;
    if (e >= E) return;
    int d = dst[e];
    int p = atomicAdd(&g_cursor[d], 1);
    g_col[p] = src[e];
}

// ---------------- GEMM1: h1[N,128] = x[N,512] @ W1[512,128] ------------------
// BM=64, BN=128(full), BK=16, 256 threads; thread tile 8(M) x 4(N) using
// packed fma.rn.f32x2 (2 FMA/instr on the fma pipe).
__global__ __launch_bounds__(256) void k_gemm1(const float* __restrict__ X,
                                               const float* __restrict__ W) {
    __shared__ float As[16][65];    // transposed A tile, padded
    __shared__ float Bs[16][128];

    int tid  = threadIdx.x;
    int bm   = blockIdx.x * 64;
    int tidm = tid >> 5;            // 0..7  (warp id)
    int lane = tid & 31;            // 0..31

    // global load mapping
    int arow = tid >> 2;            // 0..63
    int acol = (tid & 3) << 2;      // 0,4,8,12
    int brow = tid >> 4;            // 0..15
    int bcol = (tid & 15) << 3;     // 0..120

    int xrow = bm + arow;
    if (xrow >= N_NODES) xrow = N_NODES - 1;   // clamp; stores are predicated
    const float* xbase = X + (size_t)xrow * IN_F + acol;

    unsigned long long acc[8][2];
#pragma unroll
    for (int i = 0; i < 8; i++) { acc[i][0] = 0ull; acc[i][1] = 0ull; }

    for (int k0 = 0; k0 < IN_F; k0 += 16) {
        float4 av = *reinterpret_cast<const float4*>(xbase + k0);
        As[acol + 0][arow] = av.x;
        As[acol + 1][arow] = av.y;
        As[acol + 2][arow] = av.z;
        As[acol + 3][arow] = av.w;
        const float* wb = W + (size_t)(k0 + brow) * HID + bcol;
        *reinterpret_cast<float4*>(&Bs[brow][bcol])     = *reinterpret_cast<const float4*>(wb);
        *reinterpret_cast<float4*>(&Bs[brow][bcol + 4]) = *reinterpret_cast<const float4*>(wb + 4);
        __syncthreads();

#pragma unroll
        for (int kk = 0; kk < 16; kk++) {
            float a[8];
#pragma unroll
            for (int i = 0; i < 8; i++) a[i] = As[kk][tidm * 8 + i];
            unsigned long long b0 = *reinterpret_cast<const unsigned long long*>(&Bs[kk][lane * 4]);
            unsigned long long b1 = *reinterpret_cast<const unsigned long long*>(&Bs[kk][lane * 4 + 2]);
#pragma unroll
            for (int i = 0; i < 8; i++) {
                unsigned long long aa;
                asm("mov.b64 %0, {%1, %1};" : "=l"(aa) : "f"(a[i]));
                asm("fma.rn.f32x2 %0, %1, %2, %0;" : "+l"(acc[i][0]) : "l"(aa), "l"(b0));
                asm("fma.rn.f32x2 %0, %1, %2, %0;" : "+l"(acc[i][1]) : "l"(aa), "l"(b1));
            }
        }
        __syncthreads();
    }

#pragma unroll
    for (int i = 0; i < 8; i++) {
        int row = bm + tidm * 8 + i;
        if (row < N_NODES) {
            float4 o;
            o.x = __uint_as_float((unsigned)(acc[i][0] & 0xffffffffull));
            o.y = __uint_as_float((unsigned)(acc[i][0] >> 32));
            o.z = __uint_as_float((unsigned)(acc[i][1] & 0xffffffffull));
            o.w = __uint_as_float((unsigned)(acc[i][1] >> 32));
            *reinterpret_cast<float4*>(&g_h1[(size_t)row * HID + lane * 4]) = o;
        }
    }
}

// ---------------- SpMM layer 1: a1 = relu(dinv[d]*(sum dinv[s]*h1[s]) + dinv[d]^2*h1[d] + b1)
// one warp per row; each lane owns 4 of 128 features (float4).
__global__ void k_spmm1(const float* __restrict__ b1) {
    int warp = (blockIdx.x * blockDim.x + threadIdx.x) >> 5;
    int lane = threadIdx.x & 31;
    if (warp >= N_NODES) return;
    int row   = warp;
    int start = g_rowstart[row];
    int cnt   = g_cnt[row];

    const float4* H = reinterpret_cast<const float4*>(g_h1);
    float4 acc = make_float4(0.f, 0.f, 0.f, 0.f);

    if (cnt > 0) {
        int s = g_col[start];
        for (int i = 0; i < cnt; i++) {
            int snext = (i + 1 < cnt) ? g_col[start + i + 1] : 0;
            float w   = g_dinv[s];
            float4 hv = H[(size_t)s * 32 + lane];
            acc.x = fmaf(w, hv.x, acc.x);
            acc.y = fmaf(w, hv.y, acc.y);
            acc.z = fmaf(w, hv.z, acc.z);
            acc.w = fmaf(w, hv.w, acc.w);
            s = snext;
        }
    }
    float d   = g_dinv[row];
    float dd  = d * d;
    float4 hs = H[(size_t)row * 32 + lane];
    float4 bb = reinterpret_cast<const float4*>(b1)[lane];
    float4 r;
    r.x = fmaxf(fmaf(d, acc.x, dd * hs.x) + bb.x, 0.f);
    r.y = fmaxf(fmaf(d, acc.y, dd * hs.y) + bb.y, 0.f);
    r.z = fmaxf(fmaf(d, acc.z, dd * hs.z) + bb.z, 0.f);
    r.w = fmaxf(fmaf(d, acc.w, dd * hs.w) + bb.w, 0.f);
    reinterpret_cast<float4*>(g_a1)[(size_t)row * 32 + lane] = r;
}

// ---------------- GEMM2: h2[N,32] = a1[N,128] @ W2[128,32] -------------------
// 32 rows per block, W2 and A tile in shared.
__global__ __launch_bounds__(256) void k_gemm2(const float* __restrict__ W2) {
    __shared__ float As[32 * 132];   // stride 132 floats (16B-aligned rows, conflict-free)
    __shared__ float Ws[128 * 32];

    int t    = threadIdx.x;
    int row0 = blockIdx.x * 32;

    // load W2 (4096 floats) and A tile (4096 floats), 4 float4 per thread each
#pragma unroll
    for (int q = 0; q < 4; q++) {
        int f4 = t + 256 * q;
        *reinterpret_cast<float4*>(&Ws[f4 * 4]) =
            *reinterpret_cast<const float4*>(&W2[f4 * 4]);
        int r  = f4 >> 5;          // 0..31
        int c4 = f4 & 31;          // 0..31
        float4 av = *reinterpret_cast<const float4*>(
            &g_a1[(size_t)(row0 + r) * HID + c4 * 4]);
        *reinterpret_cast<float4*>(&As[r * 132 + c4 * 4]) = av;
    }
    __syncthreads();

    int r  = t >> 3;               // 0..31
    int cg = t & 7;                // 0..7 -> cols cg*4..cg*4+3
    float4 acc = make_float4(0.f, 0.f, 0.f, 0.f);
#pragma unroll 4
    for (int k = 0; k < HID; k += 4) {
        float4 a4 = *reinterpret_cast<const float4*>(&As[r * 132 + k]);
        float am[4] = {a4.x, a4.y, a4.z, a4.w};
#pragma unroll
        for (int kk = 0; kk < 4; kk++) {
            float4 w = *reinterpret_cast<const float4*>(&Ws[(k + kk) * 32 + cg * 4]);
            acc.x = fmaf(am[kk], w.x, acc.x);
            acc.y = fmaf(am[kk], w.y, acc.y);
            acc.z = fmaf(am[kk], w.z, acc.z);
            acc.w = fmaf(am[kk], w.w, acc.w);
        }
    }
    *reinterpret_cast<float4*>(&g_h2[(size_t)(row0 + r) * NCLS + cg * 4]) = acc;
}

// ---------------- SpMM layer 2: out = dinv[d]*(sum dinv[s]*h2[s]) + dinv[d]^2*h2[d] + b2
// one warp per row; each lane owns 1 of 32 classes.
__global__ void k_spmm2(const float* __restrict__ b2, float* __restrict__ out) {
    int warp = (blockIdx.x * blockDim.x + threadIdx.x) >> 5;
    int lane = threadIdx.x & 31;
    if (warp >= N_NODES) return;
    int row   = warp;
    int start = g_rowstart[row];
    int cnt   = g_cnt[row];

    float acc = 0.f;
    if (cnt > 0) {
        int s = g_col[start];
        for (int i = 0; i < cnt; i++) {
            int snext = (i + 1 < cnt) ? g_col[start + i + 1] : 0;
            float w = g_dinv[s];
            acc = fmaf(w, g_h2[(size_t)s * NCLS + lane], acc);
            s = snext;
        }
    }
    float d = g_dinv[row];
    out[(size_t)row * NCLS + lane] =
        fmaf(d, acc, d * d * g_h2[(size_t)row * NCLS + lane]) + b2[lane];
}

// ---------------- launch ------------------------------------------------------
extern "C" void kernel_launch(void* const* d_in, const int* in_sizes, int n_in,
                              void* d_out, int out_size) {
    const float* x  = (const float*)d_in[0];
    const int*   ei = (const int*)d_in[1];
    const float* W1 = (const float*)d_in[2];
    const float* b1 = (const float*)d_in[3];
    const float* W2 = (const float*)d_in[4];
    const float* b2 = (const float*)d_in[5];
    float* out = (float*)d_out;

    int E = in_sizes[1] / 2;
    const int* src = ei;
    const int* dst = ei + E;

    int nScanBlocks = (N_NODES + 1023) / 1024;   // 98

    k_zero_cnt<<<(N_NODES + 255) / 256, 256>>>();
    k_hist<<<(E + 255) / 256, 256>>>(dst, E);
    k_scan1<<<nScanBlocks, 256>>>();
    k_scan2<<<1, 128>>>(nScanBlocks);
    k_scan3<<<(N_NODES + 255) / 256, 256>>>();
    k_fill<<<(E + 255) / 256, 256>>>(src, dst, E);

    k_gemm1<<<(N_NODES + 63) / 64, 256>>>(x, W1);
    k_spmm1<<<(N_NODES + 7) / 8, 256>>>(b1);
    k_gemm2<<<N_NODES / 32, 256>>>(W2);
    k_spmm2<<<(N_NODES + 7) / 8, 256>>>(b2, out);
}

// round 3
// speedup vs baseline: 1.4165x; 1.4165x over previous
#include <cuda_runtime.h>
#include <cuda_bf16.h>
#include <cstdint>

#define N_NODES 100000
#define E_MAX   1600000
#define IN_F    512
#define HID     128
#define NCLS    32

// ---------------- scratch (device globals; no allocation allowed) ------------
__device__ int   g_cnt[N_NODES];
__device__ int   g_rowstart[N_NODES];
__device__ int   g_cursor[N_NODES];
__device__ float g_dinv[N_NODES];
__device__ int   g_col[E_MAX];
__device__ float g_h1[(size_t)N_NODES * HID];
__device__ float g_a1[(size_t)N_NODES * HID];
__device__ float g_h2[(size_t)N_NODES * NCLS];
__device__ int   g_blocksums[128];
// W1 transposed to [N=128][K=512], split into bf16 hi/lo
__device__ __nv_bfloat16 g_whi[HID * IN_F];
__device__ __nv_bfloat16 g_wlo[HID * IN_F];

__device__ __forceinline__ uint32_t smem_u32(const void* p) {
    uint32_t a;
    asm("{ .reg .u64 t; cvta.to.shared.u64 t, %1; cvt.u32.u64 %0, t; }"
        : "=r"(a) : "l"(p));
    return a;
}

__device__ __forceinline__ void cvt_hl(float x, float y, uint32_t& h, uint32_t& l) {
    __nv_bfloat162 hb = __float22bfloat162_rn(make_float2(x, y));
    float2 bk = __bfloat1622float2(hb);
    __nv_bfloat162 lb = __float22bfloat162_rn(make_float2(x - bk.x, y - bk.y));
    h = *reinterpret_cast<uint32_t*>(&hb);
    l = *reinterpret_cast<uint32_t*>(&lb);
}

__device__ __forceinline__ void ldsm_x4(uint32_t* r, uint32_t addr) {
    asm volatile("ldmatrix.sync.aligned.m8n8.x4.shared.b16 {%0,%1,%2,%3}, [%4];"
                 : "=r"(r[0]), "=r"(r[1]), "=r"(r[2]), "=r"(r[3]) : "r"(addr));
}

__device__ __forceinline__ void mma16816(float* d, const uint32_t* a, const uint32_t* b) {
    asm volatile(
        "mma.sync.aligned.m16n8k16.row.col.f32.bf16.bf16.f32 "
        "{%0,%1,%2,%3}, {%4,%5,%6,%7}, {%8,%9}, {%0,%1,%2,%3};"
        : "+f"(d[0]), "+f"(d[1]), "+f"(d[2]), "+f"(d[3])
        : "r"(a[0]), "r"(a[1]), "r"(a[2]), "r"(a[3]), "r"(b[0]), "r"(b[1]));
}

// ---------------- small helpers ------------------------------------------
__global__ void k_zero_cnt() {
    int i = blockIdx.x * blockDim.x + threadIdx.x;
    if (i < N_NODES) g_cnt[i] = 0;
}

__global__ void k_hist(const int* __restrict__ dst, int E) {
    int e = blockIdx.x * blockDim.x + threadIdx.x;
    if (e < E) atomicAdd(&g_cnt[dst[e]], 1);
}

// W1 [512][128] -> transpose + bf16 split -> g_whi/g_wlo [128][512]
__global__ void k_prepw(const float* __restrict__ W1) {
    __shared__ float sh[32][33];
    int bi = blockIdx.x & 15;        // k tile
    int bj = blockIdx.x >> 4;        // n tile
    int k0 = bi * 32, n0 = bj * 32;
    int t = threadIdx.x;
    int i = t >> 5, j = t & 31;
#pragma unroll
    for (int r = 0; r < 4; r++) {
        int kk = i + r * 8;
        sh[kk][j] = W1[(size_t)(k0 + kk) * HID + n0 + j];
    }
    __syncthreads();
#pragma unroll
    for (int r = 0; r < 4; r++) {
        int nn = i + r * 8;
        float v = sh[j][nn];
        __nv_bfloat16 h = __float2bfloat16(v);
        float rem = v - __bfloat162float(h);
        g_whi[(size_t)(n0 + nn) * IN_F + k0 + j] = h;
        g_wlo[(size_t)(n0 + nn) * IN_F + k0 + j] = __float2bfloat16(rem);
    }
}

__global__ void k_scan1() {
    __shared__ int sh[256];
    int b = blockIdx.x, t = threadIdx.x;
    int base = b * 1024 + t * 4;
    int v[4];
    int local = 0;
#pragma unroll
    for (int q = 0; q < 4; q++) {
        int i = base + q;
        v[q] = (i < N_NODES) ? g_cnt[i] : 0;
        local += v[q];
    }
    sh[t] = local;
    __syncthreads();
#pragma unroll
    for (int off = 1; off < 256; off <<= 1) {
        int add = (t >= off) ? sh[t - off] : 0;
        __syncthreads();
        sh[t] += add;
        __syncthreads();
    }
    int run = sh[t] - local;
    if (t == 255) g_blocksums[b] = sh[255];
#pragma unroll
    for (int q = 0; q < 4; q++) {
        int i = base + q;
        if (i < N_NODES) g_rowstart[i] = run;
        run += v[q];
    }
}

__global__ void k_scan2(int nblk) {
    __shared__ int sh[128];
    int t = threadIdx.x;
    int v = (t < nblk) ? g_blocksums[t] : 0;
    sh[t] = v;
    __syncthreads();
#pragma unroll
    for (int off = 1; off < 128; off <<= 1) {
        int add = (t >= off) ? sh[t - off] : 0;
        __syncthreads();
        sh[t] += add;
        __syncthreads();
    }
    if (t < nblk) g_blocksums[t] = sh[t] - v;
}

__global__ void k_scan3() {
    int i = blockIdx.x * blockDim.x + threadIdx.x;
    if (i >= N_NODES) return;
    int rs = g_rowstart[i] + g_blocksums[i >> 10];
    g_rowstart[i] = rs;
    g_cursor[i]   = rs;
    g_dinv[i]     = rsqrtf((float)(g_cnt[i] + 1));
}

__global__ void k_fill(const int* __restrict__ src, const int* __restrict__ dst, int E) {
    int e = blockIdx.x * blockDim.x + threadIdx.x;
    if (e >= E) return;
    int d = dst[e];
    int p = atomicAdd(&g_cursor[d], 1);
    g_col[p] = src[e];
}

// ---------------- GEMM1: h1 = X @ W1 via mma.sync bf16 3-pass split ----------
// Per CTA: M=128, N=128(full), K chunks of 32, double-buffered smem.
// smem stage layout (stride 40 bf16 = 80B rows, conflict-free for ldmatrix):
//   Ah[128][40] (10240 B) | Al (10240) | Bh[128][40] (10240) | Bl (10240)
#define G1_STAGE   40960
#define G1_SMEM    (2 * G1_STAGE)

__global__ __launch_bounds__(256, 1) void k_gemm1_mma(const float* __restrict__ X) {
    extern __shared__ char smem[];
    uint32_t sb = smem_u32(smem);

    const int tid  = threadIdx.x;
    const int wid  = tid >> 5;
    const int lane = tid & 31;
    const int bm   = blockIdx.x * 128;
    const int wm   = wid & 3;    // 0..3 -> m tile of 32
    const int wn   = wid >> 2;   // 0..1 -> n tile of 64

    // staging regs
    float4 aR[4];
    uint4  bhR[2], blR[2];

    const int arow_l = tid >> 1;          // 0..127
    const int ahalf  = tid & 1;
    int arow_g = bm + arow_l;
    if (arow_g >= N_NODES) arow_g = N_NODES - 1;
    const float* aptr = X + (size_t)arow_g * IN_F + ahalf * 16;

    const int bn = tid >> 1;              // 0..127
    const int bp = tid & 1;
    const __nv_bfloat16* bhp = g_whi + (size_t)bn * IN_F + bp * 16;
    const __nv_bfloat16* blp = g_wlo + (size_t)bn * IN_F + bp * 16;

    float acc[2][8][4];
#pragma unroll
    for (int m = 0; m < 2; m++)
#pragma unroll
        for (int n = 0; n < 8; n++)
#pragma unroll
            for (int q = 0; q < 4; q++) acc[m][n][q] = 0.f;

#define LDG_CHUNK(c) do { \
        const float4* p4 = (const float4*)(aptr + (c) * 32); \
        aR[0] = p4[0]; aR[1] = p4[1]; aR[2] = p4[2]; aR[3] = p4[3]; \
        const uint4* ph = (const uint4*)(bhp + (c) * 32); \
        const uint4* pl = (const uint4*)(blp + (c) * 32); \
        bhR[0] = ph[0]; bhR[1] = ph[1]; blR[0] = pl[0]; blR[1] = pl[1]; \
    } while (0)

#define STS_STAGE(s) do { \
        char* stg = smem + (s) * G1_STAGE; \
        uint32_t hw[8], lw[8]; \
        cvt_hl(aR[0].x, aR[0].y, hw[0], lw[0]); \
        cvt_hl(aR[0].z, aR[0].w, hw[1], lw[1]); \
        cvt_hl(aR[1].x, aR[1].y, hw[2], lw[2]); \
        cvt_hl(aR[1].z, aR[1].w, hw[3], lw[3]); \
        cvt_hl(aR[2].x, aR[2].y, hw[4], lw[4]); \
        cvt_hl(aR[2].z, aR[2].w, hw[5], lw[5]); \
        cvt_hl(aR[3].x, aR[3].y, hw[6], lw[6]); \
        cvt_hl(aR[3].z, aR[3].w, hw[7], lw[7]); \
        uint4* ah4 = (uint4*)(stg + arow_l * 80 + ahalf * 32); \
        uint4* al4 = (uint4*)(stg + 10240 + arow_l * 80 + ahalf * 32); \
        ah4[0] = make_uint4(hw[0], hw[1], hw[2], hw[3]); \
        ah4[1] = make_uint4(hw[4], hw[5], hw[6], hw[7]); \
        al4[0] = make_uint4(lw[0], lw[1], lw[2], lw[3]); \
        al4[1] = make_uint4(lw[4], lw[5], lw[6], lw[7]); \
        uint4* bh4 = (uint4*)(stg + 20480 + bn * 80 + bp * 32); \
        uint4* bl4 = (uint4*)(stg + 30720 + bn * 80 + bp * 32); \
        bh4[0] = bhR[0]; bh4[1] = bhR[1]; \
        bl4[0] = blR[0]; bl4[1] = blR[1]; \
    } while (0)

    LDG_CHUNK(0);
    STS_STAGE(0);
    LDG_CHUNK(1);
    __syncthreads();

    // ldmatrix lane addressing (constant across chunks, offset by stage)
    const int a_row  = wm * 32 + (lane & 15);
    const int a_koff = (lane >> 4) * 8;
    const int b_n    = wn * 64 + ((lane >> 4) & 1) * 8 + (lane & 7);
    const int b_koff = ((lane >> 3) & 1) * 8;

    for (int c = 0; c < 16; c++) {
        const int s = c & 1;
        uint32_t abase = sb + s * G1_STAGE;
        uint32_t bbase = abase + 20480;

#pragma unroll
        for (int ks = 0; ks < 2; ks++) {
            uint32_t ah[2][4], al[2][4];
#pragma unroll
            for (int m = 0; m < 2; m++) {
                uint32_t ad = abase + (uint32_t)((a_row + m * 16) * 80 + (a_koff + ks * 16) * 2);
                ldsm_x4(ah[m], ad);
                ldsm_x4(al[m], ad + 10240);
            }
            uint32_t bh[8][2], bl[8][2];
#pragma unroll
            for (int t4 = 0; t4 < 4; t4++) {
                uint32_t bd = bbase + (uint32_t)((b_n + t4 * 16) * 80 + (b_koff + ks * 16) * 2);
                uint32_t r[4], r2[4];
                ldsm_x4(r, bd);
                ldsm_x4(r2, bd + 10240);
                bh[t4 * 2 + 0][0] = r[0];  bh[t4 * 2 + 0][1] = r[1];
                bh[t4 * 2 + 1][0] = r[2];  bh[t4 * 2 + 1][1] = r[3];
                bl[t4 * 2 + 0][0] = r2[0]; bl[t4 * 2 + 0][1] = r2[1];
                bl[t4 * 2 + 1][0] = r2[2]; bl[t4 * 2 + 1][1] = r2[3];
            }
#pragma unroll
            for (int m = 0; m < 2; m++)
#pragma unroll
                for (int n = 0; n < 8; n++) {
                    mma16816(acc[m][n], ah[m], bh[n]);
                    mma16816(acc[m][n], ah[m], bl[n]);
                    mma16816(acc[m][n], al[m], bh[n]);
                }
        }

        if (c < 15) {
            STS_STAGE(s ^ 1);
            __syncthreads();
            if (c < 14) LDG_CHUNK(c + 2);
        }
    }

    // epilogue
    const int gid = lane >> 2, tig = lane & 3;
#pragma unroll
    for (int m = 0; m < 2; m++) {
        int r0 = bm + wm * 32 + m * 16 + gid;
#pragma unroll
        for (int n = 0; n < 8; n++) {
            int col = wn * 64 + n * 8 + tig * 2;
            if (r0 < N_NODES)
                *(float2*)&g_h1[(size_t)r0 * HID + col] = make_float2(acc[m][n][0], acc[m][n][1]);
            if (r0 + 8 < N_NODES)
                *(float2*)&g_h1[(size_t)(r0 + 8) * HID + col] = make_float2(acc[m][n][2], acc[m][n][3]);
        }
    }
#undef LDG_CHUNK
#undef STS_STAGE
}

// ---------------- SpMM layer 1 ------------------------------------------------
__global__ void k_spmm1(const float* __restrict__ b1) {
    int warp = (blockIdx.x * blockDim.x + threadIdx.x) >> 5;
    int lane = threadIdx.x & 31;
    if (warp >= N_NODES) return;
    int row   = warp;
    int start = g_rowstart[row];
    int cnt   = g_cnt[row];

    const float4* H = reinterpret_cast<const float4*>(g_h1);
    float4 acc = make_float4(0.f, 0.f, 0.f, 0.f);

    if (cnt > 0) {
        int s = g_col[start];
        for (int i = 0; i < cnt; i++) {
            int snext = (i + 1 < cnt) ? g_col[start + i + 1] : 0;
            float w   = g_dinv[s];
            float4 hv = H[(size_t)s * 32 + lane];
            acc.x = fmaf(w, hv.x, acc.x);
            acc.y = fmaf(w, hv.y, acc.y);
            acc.z = fmaf(w, hv.z, acc.z);
            acc.w = fmaf(w, hv.w, acc.w);
            s = snext;
        }
    }
    float d   = g_dinv[row];
    float dd  = d * d;
    float4 hs = H[(size_t)row * 32 + lane];
    float4 bb = reinterpret_cast<const float4*>(b1)[lane];
    float4 r;
    r.x = fmaxf(fmaf(d, acc.x, dd * hs.x) + bb.x, 0.f);
    r.y = fmaxf(fmaf(d, acc.y, dd * hs.y) + bb.y, 0.f);
    r.z = fmaxf(fmaf(d, acc.z, dd * hs.z) + bb.z, 0.f);
    r.w = fmaxf(fmaf(d, acc.w, dd * hs.w) + bb.w, 0.f);
    reinterpret_cast<float4*>(g_a1)[(size_t)row * 32 + lane] = r;
}

// ---------------- GEMM2: h2[N,32] = a1[N,128] @ W2[128,32] -------------------
__global__ __launch_bounds__(256) void k_gemm2(const float* __restrict__ W2) {
    __shared__ float As[32 * 132];
    __shared__ float Ws[128 * 32];

    int t    = threadIdx.x;
    int row0 = blockIdx.x * 32;

#pragma unroll
    for (int q = 0; q < 4; q++) {
        int f4 = t + 256 * q;
        *reinterpret_cast<float4*>(&Ws[f4 * 4]) =
            *reinterpret_cast<const float4*>(&W2[f4 * 4]);
        int r  = f4 >> 5;
        int c4 = f4 & 31;
        float4 av = *reinterpret_cast<const float4*>(
            &g_a1[(size_t)(row0 + r) * HID + c4 * 4]);
        *reinterpret_cast<float4*>(&As[r * 132 + c4 * 4]) = av;
    }
    __syncthreads();

    int r  = t >> 3;
    int cg = t & 7;
    float4 acc = make_float4(0.f, 0.f, 0.f, 0.f);
#pragma unroll 4
    for (int k = 0; k < HID; k += 4) {
        float4 a4 = *reinterpret_cast<const float4*>(&As[r * 132 + k]);
        float am[4] = {a4.x, a4.y, a4.z, a4.w};
#pragma unroll
        for (int kk = 0; kk < 4; kk++) {
            float4 w = *reinterpret_cast<const float4*>(&Ws[(k + kk) * 32 + cg * 4]);
            acc.x = fmaf(am[kk], w.x, acc.x);
            acc.y = fmaf(am[kk], w.y, acc.y);
            acc.z = fmaf(am[kk], w.z, acc.z);
            acc.w = fmaf(am[kk], w.w, acc.w);
        }
    }
    *reinterpret_cast<float4*>(&g_h2[(size_t)(row0 + r) * NCLS + cg * 4]) = acc;
}

// ---------------- SpMM layer 2 ------------------------------------------------
__global__ void k_spmm2(const float* __restrict__ b2, float* __restrict__ out) {
    int warp = (blockIdx.x * blockDim.x + threadIdx.x) >> 5;
    int lane = threadIdx.x & 31;
    if (warp >= N_NODES) return;
    int row   = warp;
    int start = g_rowstart[row];
    int cnt   = g_cnt[row];

    float acc = 0.f;
    if (cnt > 0) {
        int s = g_col[start];
        for (int i = 0; i < cnt; i++) {
            int snext = (i + 1 < cnt) ? g_col[start + i + 1] : 0;
            float w = g_dinv[s];
            acc = fmaf(w, g_h2[(size_t)s * NCLS + lane], acc);
            s = snext;
        }
    }
    float d = g_dinv[row];
    out[(size_t)row * NCLS + lane] =
        fmaf(d, acc, d * d * g_h2[(size_t)row * NCLS + lane]) + b2[lane];
}

// ---------------- launch ------------------------------------------------------
extern "C" void kernel_launch(void* const* d_in, const int* in_sizes, int n_in,
                              void* d_out, int out_size) {
    const float* x  = (const float*)d_in[0];
    const int*   ei = (const int*)d_in[1];
    const float* W1 = (const float*)d_in[2];
    const float* b1 = (const float*)d_in[3];
    const float* W2 = (const float*)d_in[4];
    const float* b2 = (const float*)d_in[5];
    float* out = (float*)d_out;

    int E = in_sizes[1] / 2;
    const int* src = ei;
    const int* dst = ei + E;

    int nScanBlocks = (N_NODES + 1023) / 1024;   // 98

    static bool attr_set = false;
    if (!attr_set) {
        cudaFuncSetAttribute(k_gemm1_mma,
                             cudaFuncAttributeMaxDynamicSharedMemorySize,
                             G1_SMEM);
        attr_set = true;
    }

    k_prepw<<<64, 256>>>(W1);
    k_zero_cnt<<<(N_NODES + 255) / 256, 256>>>();
    k_hist<<<(E + 255) / 256, 256>>>(dst, E);
    k_gemm1_mma<<<(N_NODES + 127) / 128, 256, G1_SMEM>>>(x);
    k_scan1<<<nScanBlocks, 256>>>();
    k_scan2<<<1, 128>>>(nScanBlocks);
    k_scan3<<<(N_NODES + 255) / 256, 256>>>();
    k_fill<<<(E + 255) / 256, 256>>>(src, dst, E);

    k_spmm1<<<(N_NODES + 7) / 8, 256>>>(b1);
    k_gemm2<<<N_NODES / 32, 256>>>(W2);
    k_spmm2<<<(N_NODES + 7) / 8, 256>>>(b2, out);
}

// round 4
// speedup vs baseline: 1.5758x; 1.1124x over previous
#include <cuda_runtime.h>
#include <cuda_bf16.h>
#include <cuda_fp16.h>
#include <cstdint>

#define N_NODES 100000
#define E_MAX   1600000
#define IN_F    512
#define HID     128
#define NCLS    32

// ---------------- scratch (device globals; no allocation allowed) ------------
__device__ int    g_cnt[N_NODES];
__device__ int    g_rowstart[N_NODES];
__device__ int    g_cursor[N_NODES];
__device__ float  g_dinv[N_NODES];
__device__ int    g_col[E_MAX];
__device__ __half g_h1h[(size_t)N_NODES * HID];   // x @ W1 (fp16)
__device__ float  g_a1[(size_t)N_NODES * HID];    // relu(agg1 + b1) fp32
__device__ __half g_h2h[(size_t)N_NODES * NCLS];  // a1 @ W2 (fp16)
__device__ int    g_blocksums[128];
// W1 transposed to [N=128][K=512], split into bf16 hi/lo
__device__ __nv_bfloat16 g_whi[HID * IN_F];
__device__ __nv_bfloat16 g_wlo[HID * IN_F];

__device__ __forceinline__ uint32_t smem_u32(const void* p) {
    uint32_t a;
    asm("{ .reg .u64 t; cvta.to.shared.u64 t, %1; cvt.u32.u64 %0, t; }"
        : "=r"(a) : "l"(p));
    return a;
}

__device__ __forceinline__ void cvt_hl(float x, float y, uint32_t& h, uint32_t& l) {
    __nv_bfloat162 hb = __float22bfloat162_rn(make_float2(x, y));
    float2 bk = __bfloat1622float2(hb);
    __nv_bfloat162 lb = __float22bfloat162_rn(make_float2(x - bk.x, y - bk.y));
    h = *reinterpret_cast<uint32_t*>(&hb);
    l = *reinterpret_cast<uint32_t*>(&lb);
}

__device__ __forceinline__ void ldsm_x4(uint32_t* r, uint32_t addr) {
    asm volatile("ldmatrix.sync.aligned.m8n8.x4.shared.b16 {%0,%1,%2,%3}, [%4];"
                 : "=r"(r[0]), "=r"(r[1]), "=r"(r[2]), "=r"(r[3]) : "r"(addr));
}

__device__ __forceinline__ void mma16816(float* d, const uint32_t* a, const uint32_t* b) {
    asm volatile(
        "mma.sync.aligned.m16n8k16.row.col.f32.bf16.bf16.f32 "
        "{%0,%1,%2,%3}, {%4,%5,%6,%7}, {%8,%9}, {%0,%1,%2,%3};"
        : "+f"(d[0]), "+f"(d[1]), "+f"(d[2]), "+f"(d[3])
        : "r"(a[0]), "r"(a[1]), "r"(a[2]), "r"(a[3]), "r"(b[0]), "r"(b[1]));
}

__device__ __forceinline__ void cpasync16(uint32_t dst, const void* src) {
    size_t g = __cvta_generic_to_global(src);
    asm volatile("cp.async.cg.shared.global [%0], [%1], 16;" :: "r"(dst), "l"(g));
}

// ---------------- small helpers ------------------------------------------
__global__ void k_zero_cnt() {
    int i = blockIdx.x * blockDim.x + threadIdx.x;
    if (i < N_NODES) g_cnt[i] = 0;
}

__global__ void k_hist(const int* __restrict__ dst, int E) {
    int e = blockIdx.x * blockDim.x + threadIdx.x;
    if (e < E) atomicAdd(&g_cnt[dst[e]], 1);
}

// W1 [512][128] -> transpose + bf16 split -> g_whi/g_wlo [128][512]
__global__ void k_prepw(const float* __restrict__ W1) {
    __shared__ float sh[32][33];
    int bi = blockIdx.x & 15;        // k tile
    int bj = blockIdx.x >> 4;        // n tile
    int k0 = bi * 32, n0 = bj * 32;
    int t = threadIdx.x;
    int i = t >> 5, j = t & 31;
#pragma unroll
    for (int r = 0; r < 4; r++) {
        int kk = i + r * 8;
        sh[kk][j] = W1[(size_t)(k0 + kk) * HID + n0 + j];
    }
    __syncthreads();
#pragma unroll
    for (int r = 0; r < 4; r++) {
        int nn = i + r * 8;
        float v = sh[j][nn];
        __nv_bfloat16 h = __float2bfloat16(v);
        float rem = v - __bfloat162float(h);
        g_whi[(size_t)(n0 + nn) * IN_F + k0 + j] = h;
        g_wlo[(size_t)(n0 + nn) * IN_F + k0 + j] = __float2bfloat16(rem);
    }
}

__global__ void k_scan1() {
    __shared__ int sh[256];
    int b = blockIdx.x, t = threadIdx.x;
    int base = b * 1024 + t * 4;
    int v[4];
    int local = 0;
#pragma unroll
    for (int q = 0; q < 4; q++) {
        int i = base + q;
        v[q] = (i < N_NODES) ? g_cnt[i] : 0;
        local += v[q];
    }
    sh[t] = local;
    __syncthreads();
#pragma unroll
    for (int off = 1; off < 256; off <<= 1) {
        int add = (t >= off) ? sh[t - off] : 0;
        __syncthreads();
        sh[t] += add;
        __syncthreads();
    }
    int run = sh[t] - local;
    if (t == 255) g_blocksums[b] = sh[255];
#pragma unroll
    for (int q = 0; q < 4; q++) {
        int i = base + q;
        if (i < N_NODES) g_rowstart[i] = run;
        run += v[q];
    }
}

__global__ void k_scan2(int nblk) {
    __shared__ int sh[128];
    int t = threadIdx.x;
    int v = (t < nblk) ? g_blocksums[t] : 0;
    sh[t] = v;
    __syncthreads();
#pragma unroll
    for (int off = 1; off < 128; off <<= 1) {
        int add = (t >= off) ? sh[t - off] : 0;
        __syncthreads();
        sh[t] += add;
        __syncthreads();
    }
    if (t < nblk) g_blocksums[t] = sh[t] - v;
}

__global__ void k_scan3() {
    int i = blockIdx.x * blockDim.x + threadIdx.x;
    if (i >= N_NODES) return;
    int rs = g_rowstart[i] + g_blocksums[i >> 10];
    g_rowstart[i] = rs;
    g_cursor[i]   = rs;
    g_dinv[i]     = rsqrtf((float)(g_cnt[i] + 1));
}

__global__ void k_fill(const int* __restrict__ src, const int* __restrict__ dst, int E) {
    int e = blockIdx.x * blockDim.x + threadIdx.x;
    if (e >= E) return;
    int d = dst[e];
    int p = atomicAdd(&g_cursor[d], 1);
    g_col[p] = src[e];
}

// ---------------- GEMM1: h1 = X @ W1 via mma.sync bf16 3-pass split ----------
// BM=256, BN=128, BK=32, double-buffered. Warps: 4m x 2n; per warp mt=4, nt=8.
// Stage layout (80B row stride, conflict-free):
//   Ah[256][40] 20480 | Al 20480 | Bh[128][40] 10240 | Bl 10240  = 61440
#define G1_STAGE   61440
#define G1_SMEM    (2 * G1_STAGE)

__global__ __launch_bounds__(256, 1) void k_gemm1_mma(const float* __restrict__ X) {
    extern __shared__ char smem[];
    uint32_t sb = smem_u32(smem);

    const int tid  = threadIdx.x;
    const int wid  = tid >> 5;
    const int lane = tid & 31;
    const int bm   = blockIdx.x * 256;
    const int wm   = wid & 3;    // 0..3 -> m block of 64 rows
    const int wn   = wid >> 2;   // 0..1 -> n block of 64

    // A global load: one row per thread, 32 floats per chunk
    int arow_g = bm + tid;
    if (arow_g >= N_NODES) arow_g = N_NODES - 1;
    const float* aptr = X + (size_t)arow_g * IN_F;

    float4 aR[8];

#define LDG_A(c) do { \
        const float4* p4 = (const float4*)(aptr + (c) * 32); \
        _Pragma("unroll") \
        for (int q = 0; q < 8; q++) aR[q] = p4[q]; \
    } while (0)

#define STS_A(s) do { \
        char* stg = smem + (s) * G1_STAGE; \
        uint32_t hw[16], lw[16]; \
        _Pragma("unroll") \
        for (int q = 0; q < 8; q++) { \
            cvt_hl(aR[q].x, aR[q].y, hw[2*q],   lw[2*q]); \
            cvt_hl(aR[q].z, aR[q].w, hw[2*q+1], lw[2*q+1]); \
        } \
        uint4* ah4 = (uint4*)(stg + tid * 80); \
        uint4* al4 = (uint4*)(stg + 20480 + tid * 80); \
        _Pragma("unroll") \
        for (int j = 0; j < 4; j++) { \
            ah4[j] = make_uint4(hw[4*j], hw[4*j+1], hw[4*j+2], hw[4*j+3]); \
            al4[j] = make_uint4(lw[4*j], lw[4*j+1], lw[4*j+2], lw[4*j+3]); \
        } \
    } while (0)

#define CPA_B(c, s) do { \
        uint32_t bdst = sb + (s) * G1_STAGE + 40960; \
        _Pragma("unroll") \
        for (int q = 0; q < 2; q++) { \
            int u = tid + q * 256; \
            int row = u >> 2, j = u & 3; \
            uint32_t dh = bdst + row * 80 + j * 16; \
            cpasync16(dh, g_whi + (size_t)row * IN_F + (c) * 32 + j * 8); \
            cpasync16(dh + 10240, g_wlo + (size_t)row * IN_F + (c) * 32 + j * 8); \
        } \
        asm volatile("cp.async.commit_group;"); \
    } while (0)

    float acc[4][8][4];
#pragma unroll
    for (int m = 0; m < 4; m++)
#pragma unroll
        for (int n = 0; n < 8; n++)
#pragma unroll
            for (int q = 0; q < 4; q++) acc[m][n][q] = 0.f;

    LDG_A(0);
    STS_A(0);
    CPA_B(0, 0);
    LDG_A(1);
    asm volatile("cp.async.wait_group 0;");
    __syncthreads();

    // ldmatrix lane addressing
    const int a_row  = wm * 64 + (lane & 15);
    const int a_koff = (lane >> 4) * 8;
    const int b_n    = wn * 64 + ((lane >> 4) & 1) * 8 + (lane & 7);
    const int b_koff = ((lane >> 3) & 1) * 8;

    for (int c = 0; c < 16; c++) {
        const int s = c & 1;
        uint32_t abase = sb + s * G1_STAGE;
        uint32_t bbase = abase + 40960;

#pragma unroll
        for (int ks = 0; ks < 2; ks++) {
            uint32_t ah[4][4], al[4][4];
#pragma unroll
            for (int m = 0; m < 4; m++) {
                uint32_t ad = abase + (uint32_t)((a_row + m * 16) * 80 + (a_koff + ks * 16) * 2);
                ldsm_x4(ah[m], ad);
                ldsm_x4(al[m], ad + 20480);
            }
#pragma unroll
            for (int g = 0; g < 4; g++) {
                uint32_t bd = bbase + (uint32_t)((b_n + g * 16) * 80 + (b_koff + ks * 16) * 2);
                uint32_t rh[4], rl[4];
                ldsm_x4(rh, bd);
                ldsm_x4(rl, bd + 10240);
#pragma unroll
                for (int m = 0; m < 4; m++) {
                    mma16816(acc[m][2*g],   ah[m], rh);
                    mma16816(acc[m][2*g],   ah[m], rl);
                    mma16816(acc[m][2*g],   al[m], rh);
                    mma16816(acc[m][2*g+1], ah[m], rh + 2);
                    mma16816(acc[m][2*g+1], ah[m], rl + 2);
                    mma16816(acc[m][2*g+1], al[m], rh + 2);
                }
            }
        }

        if (c < 15) {
            STS_A(s ^ 1);
            CPA_B(c + 1, s ^ 1);
            if (c < 14) LDG_A(c + 2);
            asm volatile("cp.async.wait_group 0;");
            __syncthreads();
        }
    }

    // epilogue -> fp16 h1
    const int gid = lane >> 2, tig = lane & 3;
#pragma unroll
    for (int m = 0; m < 4; m++) {
        int r0 = bm + wm * 64 + m * 16 + gid;
#pragma unroll
        for (int n = 0; n < 8; n++) {
            int col = wn * 64 + n * 8 + tig * 2;
            if (r0 < N_NODES) {
                __half2 o = __floats2half2_rn(acc[m][n][0], acc[m][n][1]);
                *(__half2*)&g_h1h[(size_t)r0 * HID + col] = o;
            }
            if (r0 + 8 < N_NODES) {
                __half2 o = __floats2half2_rn(acc[m][n][2], acc[m][n][3]);
                *(__half2*)&g_h1h[(size_t)(r0 + 8) * HID + col] = o;
            }
        }
    }
#undef LDG_A
#undef STS_A
#undef CPA_B
}

// ---------------- SpMM layer 1 (fp16 gather, fp32 accumulate) -----------------
__global__ void k_spmm1(const float* __restrict__ b1) {
    int warp = (blockIdx.x * blockDim.x + threadIdx.x) >> 5;
    int lane = threadIdx.x & 31;
    if (warp >= N_NODES) return;
    int row   = warp;
    int start = g_rowstart[row];
    int cnt   = g_cnt[row];

    const uint2* H = reinterpret_cast<const uint2*>(g_h1h);   // 4 half / uint2
    float4 acc = make_float4(0.f, 0.f, 0.f, 0.f);

    if (cnt > 0) {
        int s = g_col[start];
        for (int i = 0; i < cnt; i++) {
            int snext = (i + 1 < cnt) ? g_col[start + i + 1] : 0;
            float w = g_dinv[s];
            uint2 hv = H[(size_t)s * 32 + lane];
            float2 f0 = __half22float2(*(__half2*)&hv.x);
            float2 f1 = __half22float2(*(__half2*)&hv.y);
            acc.x = fmaf(w, f0.x, acc.x);
            acc.y = fmaf(w, f0.y, acc.y);
            acc.z = fmaf(w, f1.x, acc.z);
            acc.w = fmaf(w, f1.y, acc.w);
            s = snext;
        }
    }
    float d  = g_dinv[row];
    float dd = d * d;
    uint2 hv = H[(size_t)row * 32 + lane];
    float2 s0 = __half22float2(*(__half2*)&hv.x);
    float2 s1 = __half22float2(*(__half2*)&hv.y);
    float4 bb = reinterpret_cast<const float4*>(b1)[lane];
    float4 r;
    r.x = fmaxf(fmaf(d, acc.x, dd * s0.x) + bb.x, 0.f);
    r.y = fmaxf(fmaf(d, acc.y, dd * s0.y) + bb.y, 0.f);
    r.z = fmaxf(fmaf(d, acc.z, dd * s1.x) + bb.z, 0.f);
    r.w = fmaxf(fmaf(d, acc.w, dd * s1.y) + bb.w, 0.f);
    reinterpret_cast<float4*>(g_a1)[(size_t)row * 32 + lane] = r;
}

// ---------------- GEMM2: h2[N,32] = a1[N,128] @ W2[128,32] -------------------
__global__ __launch_bounds__(256) void k_gemm2(const float* __restrict__ W2) {
    __shared__ float As[32 * 132];
    __shared__ float Ws[128 * 32];

    int t    = threadIdx.x;
    int row0 = blockIdx.x * 32;

#pragma unroll
    for (int q = 0; q < 4; q++) {
        int f4 = t + 256 * q;
        *reinterpret_cast<float4*>(&Ws[f4 * 4]) =
            *reinterpret_cast<const float4*>(&W2[f4 * 4]);
        int r  = f4 >> 5;
        int c4 = f4 & 31;
        float4 av = *reinterpret_cast<const float4*>(
            &g_a1[(size_t)(row0 + r) * HID + c4 * 4]);
        *reinterpret_cast<float4*>(&As[r * 132 + c4 * 4]) = av;
    }
    __syncthreads();

    int r  = t >> 3;
    int cg = t & 7;
    float4 acc = make_float4(0.f, 0.f, 0.f, 0.f);
#pragma unroll 4
    for (int k = 0; k < HID; k += 4) {
        float4 a4 = *reinterpret_cast<const float4*>(&As[r * 132 + k]);
        float am[4] = {a4.x, a4.y, a4.z, a4.w};
#pragma unroll
        for (int kk = 0; kk < 4; kk++) {
            float4 w = *reinterpret_cast<const float4*>(&Ws[(k + kk) * 32 + cg * 4]);
            acc.x = fmaf(am[kk], w.x, acc.x);
            acc.y = fmaf(am[kk], w.y, acc.y);
            acc.z = fmaf(am[kk], w.z, acc.z);
            acc.w = fmaf(am[kk], w.w, acc.w);
        }
    }
    __half2 o0 = __floats2half2_rn(acc.x, acc.y);
    __half2 o1 = __floats2half2_rn(acc.z, acc.w);
    uint2 ov = make_uint2(*(uint32_t*)&o0, *(uint32_t*)&o1);
    *reinterpret_cast<uint2*>(&g_h2h[(size_t)(row0 + r) * NCLS + cg * 4]) = ov;
}

// ---------------- SpMM layer 2 (fp16 gather) ----------------------------------
__global__ void k_spmm2(const float* __restrict__ b2, float* __restrict__ out) {
    int warp = (blockIdx.x * blockDim.x + threadIdx.x) >> 5;
    int lane = threadIdx.x & 31;
    if (warp >= N_NODES) return;
    int row   = warp;
    int start = g_rowstart[row];
    int cnt   = g_cnt[row];

    float acc = 0.f;
    if (cnt > 0) {
        int s = g_col[start];
        for (int i = 0; i < cnt; i++) {
            int snext = (i + 1 < cnt) ? g_col[start + i + 1] : 0;
            float w = g_dinv[s];
            float v = __half2float(g_h2h[(size_t)s * NCLS + lane]);
            acc = fmaf(w, v, acc);
            s = snext;
        }
    }
    float d = g_dinv[row];
    float self = __half2float(g_h2h[(size_t)row * NCLS + lane]);
    out[(size_t)row * NCLS + lane] = fmaf(d, acc, d * d * self) + b2[lane];
}

// ---------------- launch ------------------------------------------------------
extern "C" void kernel_launch(void* const* d_in, const int* in_sizes, int n_in,
                              void* d_out, int out_size) {
    const float* x  = (const float*)d_in[0];
    const int*   ei = (const int*)d_in[1];
    const float* W1 = (const float*)d_in[2];
    const float* b1 = (const float*)d_in[3];
    const float* W2 = (const float*)d_in[4];
    const float* b2 = (const float*)d_in[5];
    float* out = (float*)d_out;

    int E = in_sizes[1] / 2;
    const int* src = ei;
    const int* dst = ei + E;

    int nScanBlocks = (N_NODES + 1023) / 1024;   // 98

    static bool attr_set = false;
    if (!attr_set) {
        cudaFuncSetAttribute(k_gemm1_mma,
                             cudaFuncAttributeMaxDynamicSharedMemorySize,
                             G1_SMEM);
        attr_set = true;
    }

    k_prepw<<<64, 256>>>(W1);
    k_zero_cnt<<<(N_NODES + 255) / 256, 256>>>();
    k_hist<<<(E + 255) / 256, 256>>>(dst, E);
    k_gemm1_mma<<<(N_NODES + 255) / 256, 256, G1_SMEM>>>(x);
    k_scan1<<<nScanBlocks, 256>>>();
    k_scan2<<<1, 128>>>(nScanBlocks);
    k_scan3<<<(N_NODES + 255) / 256, 256>>>();
    k_fill<<<(E + 255) / 256, 256>>>(src, dst, E);

    k_spmm1<<<(N_NODES + 7) / 8, 256>>>(b1);
    k_gemm2<<<N_NODES / 32, 256>>>(W2);
    k_spmm2<<<(N_NODES + 7) / 8, 256>>>(b2, out);
}

// round 5
// speedup vs baseline: 1.7535x; 1.1128x over previous
#include <cuda_runtime.h>
#include <cuda_bf16.h>
#include <cuda_fp16.h>
#include <cstdint>

#define N_NODES 100000
#define E_MAX   1600000
#define IN_F    512
#define HID     128
#define NCLS    32

// ---------------- scratch (device globals; no allocation allowed) ------------
__device__ int    g_cnt[N_NODES];
__device__ int    g_rowstart[N_NODES];
__device__ int    g_cursor[N_NODES];
__device__ float  g_dinv[N_NODES];
__device__ int    g_col[E_MAX];
__device__ __half g_h1h[(size_t)N_NODES * HID];   // x @ W1 (fp16)
__device__ float  g_a1[(size_t)N_NODES * HID];    // relu(agg1 + b1) fp32
__device__ __half g_h2h[(size_t)N_NODES * NCLS];  // a1 @ W2 (fp16)
__device__ int    g_blocksums[128];
// W1 transposed to [N=128][K=512], split into bf16 hi/lo
__device__ __nv_bfloat16 g_whi[HID * IN_F];
__device__ __nv_bfloat16 g_wlo[HID * IN_F];

__device__ __forceinline__ uint32_t smem_u32(const void* p) {
    uint32_t a;
    asm("{ .reg .u64 t; cvta.to.shared.u64 t, %1; cvt.u32.u64 %0, t; }"
        : "=r"(a) : "l"(p));
    return a;
}

__device__ __forceinline__ void cvt_hl(float x, float y, uint32_t& h, uint32_t& l) {
    __nv_bfloat162 hb = __float22bfloat162_rn(make_float2(x, y));
    float2 bk = __bfloat1622float2(hb);
    __nv_bfloat162 lb = __float22bfloat162_rn(make_float2(x - bk.x, y - bk.y));
    h = *reinterpret_cast<uint32_t*>(&hb);
    l = *reinterpret_cast<uint32_t*>(&lb);
}

__device__ __forceinline__ void ldsm_x4(uint32_t* r, uint32_t addr) {
    asm volatile("ldmatrix.sync.aligned.m8n8.x4.shared.b16 {%0,%1,%2,%3}, [%4];"
                 : "=r"(r[0]), "=r"(r[1]), "=r"(r[2]), "=r"(r[3]) : "r"(addr));
}

__device__ __forceinline__ void mma16816(float* d, const uint32_t* a, const uint32_t* b) {
    asm volatile(
        "mma.sync.aligned.m16n8k16.row.col.f32.bf16.bf16.f32 "
        "{%0,%1,%2,%3}, {%4,%5,%6,%7}, {%8,%9}, {%0,%1,%2,%3};"
        : "+f"(d[0]), "+f"(d[1]), "+f"(d[2]), "+f"(d[3])
        : "r"(a[0]), "r"(a[1]), "r"(a[2]), "r"(a[3]), "r"(b[0]), "r"(b[1]));
}

__device__ __forceinline__ void cpasync16(uint32_t dst, const void* src) {
    size_t g = __cvta_generic_to_global(src);
    asm volatile("cp.async.cg.shared.global [%0], [%1], 16;" :: "r"(dst), "l"(g));
}

// ---------------- small helpers ------------------------------------------
__global__ void k_zero_cnt() {
    int i = blockIdx.x * blockDim.x + threadIdx.x;
    if (i < N_NODES) g_cnt[i] = 0;
}

__global__ void k_hist(const int* __restrict__ dst, int E) {
    int e = blockIdx.x * blockDim.x + threadIdx.x;
    if (e < E) atomicAdd(&g_cnt[dst[e]], 1);
}

// W1 [512][128] -> transpose + bf16 split -> g_whi/g_wlo [128][512]
__global__ void k_prepw(const float* __restrict__ W1) {
    __shared__ float sh[32][33];
    int bi = blockIdx.x & 15;        // k tile
    int bj = blockIdx.x >> 4;        // n tile
    int k0 = bi * 32, n0 = bj * 32;
    int t = threadIdx.x;
    int i = t >> 5, j = t & 31;
#pragma unroll
    for (int r = 0; r < 4; r++) {
        int kk = i + r * 8;
        sh[kk][j] = W1[(size_t)(k0 + kk) * HID + n0 + j];
    }
    __syncthreads();
#pragma unroll
    for (int r = 0; r < 4; r++) {
        int nn = i + r * 8;
        float v = sh[j][nn];
        __nv_bfloat16 h = __float2bfloat16(v);
        float rem = v - __bfloat162float(h);
        g_whi[(size_t)(n0 + nn) * IN_F + k0 + j] = h;
        g_wlo[(size_t)(n0 + nn) * IN_F + k0 + j] = __float2bfloat16(rem);
    }
}

__global__ void k_scan1() {
    __shared__ int sh[256];
    int b = blockIdx.x, t = threadIdx.x;
    int base = b * 1024 + t * 4;
    int v[4];
    int local = 0;
#pragma unroll
    for (int q = 0; q < 4; q++) {
        int i = base + q;
        v[q] = (i < N_NODES) ? g_cnt[i] : 0;
        local += v[q];
    }
    sh[t] = local;
    __syncthreads();
#pragma unroll
    for (int off = 1; off < 256; off <<= 1) {
        int add = (t >= off) ? sh[t - off] : 0;
        __syncthreads();
        sh[t] += add;
        __syncthreads();
    }
    int run = sh[t] - local;
    if (t == 255) g_blocksums[b] = sh[255];
#pragma unroll
    for (int q = 0; q < 4; q++) {
        int i = base + q;
        if (i < N_NODES) g_rowstart[i] = run;
        run += v[q];
    }
}

__global__ void k_scan2(int nblk) {
    __shared__ int sh[128];
    int t = threadIdx.x;
    int v = (t < nblk) ? g_blocksums[t] : 0;
    sh[t] = v;
    __syncthreads();
#pragma unroll
    for (int off = 1; off < 128; off <<= 1) {
        int add = (t >= off) ? sh[t - off] : 0;
        __syncthreads();
        sh[t] += add;
        __syncthreads();
    }
    if (t < nblk) g_blocksums[t] = sh[t] - v;
}

__global__ void k_scan3() {
    int i = blockIdx.x * blockDim.x + threadIdx.x;
    if (i >= N_NODES) return;
    int rs = g_rowstart[i] + g_blocksums[i >> 10];
    g_rowstart[i] = rs;
    g_cursor[i]   = rs;
    g_dinv[i]     = rsqrtf((float)(g_cnt[i] + 1));
}

__global__ void k_fill(const int* __restrict__ src, const int* __restrict__ dst, int E) {
    int e = blockIdx.x * blockDim.x + threadIdx.x;
    if (e >= E) return;
    int d = dst[e];
    int p = atomicAdd(&g_cursor[d], 1);
    g_col[p] = src[e];
}

// ---------------- GEMM1: h1 = X @ W1 via mma.sync bf16 3-pass split ----------
// BM=256, BN=128, BK=32, double-buffered. Warps: 4m x 2n; per warp mt=4, nt=8.
// Stage layout (80B row stride, conflict-free):
//   Ah[256][40] 20480 | Al 20480 | Bh[128][40] 10240 | Bl 10240  = 61440
#define G1_STAGE   61440
#define G1_SMEM    (2 * G1_STAGE)

__global__ __launch_bounds__(256, 1) void k_gemm1_mma(const float* __restrict__ X) {
    extern __shared__ char smem[];
    uint32_t sb = smem_u32(smem);

    const int tid  = threadIdx.x;
    const int wid  = tid >> 5;
    const int lane = tid & 31;
    const int bm   = blockIdx.x * 256;
    const int wm   = wid & 3;    // 0..3 -> m block of 64 rows
    const int wn   = wid >> 2;   // 0..1 -> n block of 64

    // A global load: one row per thread, 32 floats per chunk
    int arow_g = bm + tid;
    if (arow_g >= N_NODES) arow_g = N_NODES - 1;
    const float* aptr = X + (size_t)arow_g * IN_F;

    float4 aR[8];

#define LDG_A(c) do { \
        const float4* p4 = (const float4*)(aptr + (c) * 32); \
        _Pragma("unroll") \
        for (int q = 0; q < 8; q++) aR[q] = p4[q]; \
    } while (0)

#define STS_A(s) do { \
        char* stg = smem + (s) * G1_STAGE; \
        uint4* ah4 = (uint4*)(stg + tid * 80); \
        uint4* al4 = (uint4*)(stg + 20480 + tid * 80); \
        _Pragma("unroll") \
        for (int hblk = 0; hblk < 2; hblk++) { \
            uint32_t hw[8], lw[8]; \
            _Pragma("unroll") \
            for (int q = 0; q < 4; q++) { \
                cvt_hl(aR[hblk*4+q].x, aR[hblk*4+q].y, hw[2*q],   lw[2*q]); \
                cvt_hl(aR[hblk*4+q].z, aR[hblk*4+q].w, hw[2*q+1], lw[2*q+1]); \
            } \
            _Pragma("unroll") \
            for (int j = 0; j < 2; j++) { \
                ah4[hblk*2+j] = make_uint4(hw[4*j], hw[4*j+1], hw[4*j+2], hw[4*j+3]); \
                al4[hblk*2+j] = make_uint4(lw[4*j], lw[4*j+1], lw[4*j+2], lw[4*j+3]); \
            } \
        } \
    } while (0)

#define CPA_B(c, s) do { \
        uint32_t bdst = sb + (s) * G1_STAGE + 40960; \
        _Pragma("unroll") \
        for (int q = 0; q < 2; q++) { \
            int u = tid + q * 256; \
            int row = u >> 2, j = u & 3; \
            uint32_t dh = bdst + row * 80 + j * 16; \
            cpasync16(dh, g_whi + (size_t)row * IN_F + (c) * 32 + j * 8); \
            cpasync16(dh + 10240, g_wlo + (size_t)row * IN_F + (c) * 32 + j * 8); \
        } \
        asm volatile("cp.async.commit_group;"); \
    } while (0)

    float acc[4][8][4];
#pragma unroll
    for (int m = 0; m < 4; m++)
#pragma unroll
        for (int n = 0; n < 8; n++)
#pragma unroll
            for (int q = 0; q < 4; q++) acc[m][n][q] = 0.f;

    LDG_A(0);
    STS_A(0);
    CPA_B(0, 0);
    LDG_A(1);
    asm volatile("cp.async.wait_group 0;");
    __syncthreads();

    // ldmatrix lane addressing
    const int a_row  = wm * 64 + (lane & 15);
    const int a_koff = (lane >> 4) * 8;
    const int b_n    = wn * 64 + ((lane >> 4) & 1) * 8 + (lane & 7);
    const int b_koff = ((lane >> 3) & 1) * 8;

    for (int c = 0; c < 16; c++) {
        const int s = c & 1;
        uint32_t abase = sb + s * G1_STAGE;
        uint32_t bbase = abase + 40960;

#pragma unroll
        for (int ks = 0; ks < 2; ks++) {
            uint32_t ah[4][4], al[4][4];
#pragma unroll
            for (int m = 0; m < 4; m++) {
                uint32_t ad = abase + (uint32_t)((a_row + m * 16) * 80 + (a_koff + ks * 16) * 2);
                ldsm_x4(ah[m], ad);
                ldsm_x4(al[m], ad + 20480);
            }
#pragma unroll
            for (int g = 0; g < 4; g++) {
                uint32_t bd = bbase + (uint32_t)((b_n + g * 16) * 80 + (b_koff + ks * 16) * 2);
                uint32_t rh[4], rl[4];
                ldsm_x4(rh, bd);
                ldsm_x4(rl, bd + 10240);
#pragma unroll
                for (int m = 0; m < 4; m++) {
                    mma16816(acc[m][2*g],   ah[m], rh);
                    mma16816(acc[m][2*g],   ah[m], rl);
                    mma16816(acc[m][2*g],   al[m], rh);
                    mma16816(acc[m][2*g+1], ah[m], rh + 2);
                    mma16816(acc[m][2*g+1], ah[m], rl + 2);
                    mma16816(acc[m][2*g+1], al[m], rh + 2);
                }
            }
        }

        if (c < 15) {
            STS_A(s ^ 1);
            CPA_B(c + 1, s ^ 1);
            if (c < 14) LDG_A(c + 2);
            asm volatile("cp.async.wait_group 0;");
            __syncthreads();
        }
    }

    // epilogue -> fp16 h1
    const int gid = lane >> 2, tig = lane & 3;
#pragma unroll
    for (int m = 0; m < 4; m++) {
        int r0 = bm + wm * 64 + m * 16 + gid;
#pragma unroll
        for (int n = 0; n < 8; n++) {
            int col = wn * 64 + n * 8 + tig * 2;
            if (r0 < N_NODES) {
                __half2 o = __floats2half2_rn(acc[m][n][0], acc[m][n][1]);
                *(__half2*)&g_h1h[(size_t)r0 * HID + col] = o;
            }
            if (r0 + 8 < N_NODES) {
                __half2 o = __floats2half2_rn(acc[m][n][2], acc[m][n][3]);
                *(__half2*)&g_h1h[(size_t)(r0 + 8) * HID + col] = o;
            }
        }
    }
#undef LDG_A
#undef STS_A
#undef CPA_B
}

// ---------------- SpMM layer 1 (fp16 gather, fp32 acc, 4-way MLP) ------------
__global__ void k_spmm1(const float* __restrict__ b1) {
    int warp = (blockIdx.x * blockDim.x + threadIdx.x) >> 5;
    int lane = threadIdx.x & 31;
    if (warp >= N_NODES) return;
    int row   = warp;
    int start = g_rowstart[row];
    int cnt   = g_cnt[row];

    const uint2* H = reinterpret_cast<const uint2*>(g_h1h);
    const int* cp = g_col + start;
    float4 acc = make_float4(0.f, 0.f, 0.f, 0.f);

    int i = 0;
    for (; i + 4 <= cnt; i += 4) {
        int s0 = cp[i], s1 = cp[i + 1], s2 = cp[i + 2], s3 = cp[i + 3];
        float w0 = g_dinv[s0], w1 = g_dinv[s1], w2 = g_dinv[s2], w3 = g_dinv[s3];
        uint2 v0 = H[(size_t)s0 * 32 + lane];
        uint2 v1 = H[(size_t)s1 * 32 + lane];
        uint2 v2 = H[(size_t)s2 * 32 + lane];
        uint2 v3 = H[(size_t)s3 * 32 + lane];
#define ACCUM(vv, ww) do { \
            float2 f0 = __half22float2(*(__half2*)&(vv).x); \
            float2 f1 = __half22float2(*(__half2*)&(vv).y); \
            acc.x = fmaf((ww), f0.x, acc.x); \
            acc.y = fmaf((ww), f0.y, acc.y); \
            acc.z = fmaf((ww), f1.x, acc.z); \
            acc.w = fmaf((ww), f1.y, acc.w); \
        } while (0)
        ACCUM(v0, w0); ACCUM(v1, w1); ACCUM(v2, w2); ACCUM(v3, w3);
    }
    for (; i < cnt; i++) {
        int s = cp[i];
        float w = g_dinv[s];
        uint2 v = H[(size_t)s * 32 + lane];
        ACCUM(v, w);
    }
#undef ACCUM

    float d  = g_dinv[row];
    float dd = d * d;
    uint2 hv = H[(size_t)row * 32 + lane];
    float2 s0 = __half22float2(*(__half2*)&hv.x);
    float2 s1 = __half22float2(*(__half2*)&hv.y);
    float4 bb = reinterpret_cast<const float4*>(b1)[lane];
    float4 r;
    r.x = fmaxf(fmaf(d, acc.x, dd * s0.x) + bb.x, 0.f);
    r.y = fmaxf(fmaf(d, acc.y, dd * s0.y) + bb.y, 0.f);
    r.z = fmaxf(fmaf(d, acc.z, dd * s1.x) + bb.z, 0.f);
    r.w = fmaxf(fmaf(d, acc.w, dd * s1.y) + bb.w, 0.f);
    reinterpret_cast<float4*>(g_a1)[(size_t)row * 32 + lane] = r;
}

// ---------------- GEMM2: h2[N,32] = a1[N,128] @ W2[128,32] -------------------
__global__ __launch_bounds__(256) void k_gemm2(const float* __restrict__ W2) {
    __shared__ float As[32 * 132];
    __shared__ float Ws[128 * 32];

    int t    = threadIdx.x;
    int row0 = blockIdx.x * 32;

#pragma unroll
    for (int q = 0; q < 4; q++) {
        int f4 = t + 256 * q;
        *reinterpret_cast<float4*>(&Ws[f4 * 4]) =
            *reinterpret_cast<const float4*>(&W2[f4 * 4]);
        int r  = f4 >> 5;
        int c4 = f4 & 31;
        float4 av = *reinterpret_cast<const float4*>(
            &g_a1[(size_t)(row0 + r) * HID + c4 * 4]);
        *reinterpret_cast<float4*>(&As[r * 132 + c4 * 4]) = av;
    }
    __syncthreads();

    int r  = t >> 3;
    int cg = t & 7;
    float4 acc = make_float4(0.f, 0.f, 0.f, 0.f);
#pragma unroll 4
    for (int k = 0; k < HID; k += 4) {
        float4 a4 = *reinterpret_cast<const float4*>(&As[r * 132 + k]);
        float am[4] = {a4.x, a4.y, a4.z, a4.w};
#pragma unroll
        for (int kk = 0; kk < 4; kk++) {
            float4 w = *reinterpret_cast<const float4*>(&Ws[(k + kk) * 32 + cg * 4]);
            acc.x = fmaf(am[kk], w.x, acc.x);
            acc.y = fmaf(am[kk], w.y, acc.y);
            acc.z = fmaf(am[kk], w.z, acc.z);
            acc.w = fmaf(am[kk], w.w, acc.w);
        }
    }
    __half2 o0 = __floats2half2_rn(acc.x, acc.y);
    __half2 o1 = __floats2half2_rn(acc.z, acc.w);
    uint2 ov = make_uint2(*(uint32_t*)&o0, *(uint32_t*)&o1);
    *reinterpret_cast<uint2*>(&g_h2h[(size_t)(row0 + r) * NCLS + cg * 4]) = ov;
}

// ---------------- SpMM layer 2 (fp16 gather, 4-way MLP) -----------------------
__global__ void k_spmm2(const float* __restrict__ b2, float* __restrict__ out) {
    int warp = (blockIdx.x * blockDim.x + threadIdx.x) >> 5;
    int lane = threadIdx.x & 31;
    if (warp >= N_NODES) return;
    int row   = warp;
    int start = g_rowstart[row];
    int cnt   = g_cnt[row];
    const int* cp = g_col + start;

    float acc = 0.f;
    int i = 0;
    for (; i + 4 <= cnt; i += 4) {
        int s0 = cp[i], s1 = cp[i + 1], s2 = cp[i + 2], s3 = cp[i + 3];
        float w0 = g_dinv[s0], w1 = g_dinv[s1], w2 = g_dinv[s2], w3 = g_dinv[s3];
        float v0 = __half2float(g_h2h[(size_t)s0 * NCLS + lane]);
        float v1 = __half2float(g_h2h[(size_t)s1 * NCLS + lane]);
        float v2 = __half2float(g_h2h[(size_t)s2 * NCLS + lane]);
        float v3 = __half2float(g_h2h[(size_t)s3 * NCLS + lane]);
        acc = fmaf(w0, v0, acc);
        acc = fmaf(w1, v1, acc);
        acc = fmaf(w2, v2, acc);
        acc = fmaf(w3, v3, acc);
    }
    for (; i < cnt; i++) {
        int s = cp[i];
        acc = fmaf(g_dinv[s], __half2float(g_h2h[(size_t)s * NCLS + lane]), acc);
    }
    float d = g_dinv[row];
    float self = __half2float(g_h2h[(size_t)row * NCLS + lane]);
    out[(size_t)row * NCLS + lane] = fmaf(d, acc, d * d * self) + b2[lane];
}

// ---------------- launch ------------------------------------------------------
extern "C" void kernel_launch(void* const* d_in, const int* in_sizes, int n_in,
                              void* d_out, int out_size) {
    const float* x  = (const float*)d_in[0];
    const int*   ei = (const int*)d_in[1];
    const float* W1 = (const float*)d_in[2];
    const float* b1 = (const float*)d_in[3];
    const float* W2 = (const float*)d_in[4];
    const float* b2 = (const float*)d_in[5];
    float* out = (float*)d_out;

    int E = in_sizes[1] / 2;
    const int* src = ei;
    const int* dst = ei + E;

    int nScanBlocks = (N_NODES + 1023) / 1024;   // 98

    static cudaStream_t s2 = nullptr;
    static cudaEvent_t evFork = nullptr, evJoin = nullptr;
    static bool init_done = false;
    if (!init_done) {
        cudaFuncSetAttribute(k_gemm1_mma,
                             cudaFuncAttributeMaxDynamicSharedMemorySize,
                             G1_SMEM);
        cudaStreamCreateWithFlags(&s2, cudaStreamNonBlocking);
        cudaEventCreateWithFlags(&evFork, cudaEventDisableTiming);
        cudaEventCreateWithFlags(&evJoin, cudaEventDisableTiming);
        init_done = true;
    }

    // fork: CSR build on s2, GEMM path on the main (captured) stream
    cudaEventRecord(evFork, 0);
    cudaStreamWaitEvent(s2, evFork, 0);

    k_zero_cnt<<<(N_NODES + 255) / 256, 256, 0, s2>>>();
    k_hist<<<(E + 255) / 256, 256, 0, s2>>>(dst, E);
    k_scan1<<<nScanBlocks, 256, 0, s2>>>();
    k_scan2<<<1, 128, 0, s2>>>(nScanBlocks);
    k_scan3<<<(N_NODES + 255) / 256, 256, 0, s2>>>();
    k_fill<<<(E + 255) / 256, 256, 0, s2>>>(src, dst, E);
    cudaEventRecord(evJoin, s2);

    k_prepw<<<64, 256>>>(W1);
    k_gemm1_mma<<<(N_NODES + 255) / 256, 256, G1_SMEM>>>(x);

    // join
    cudaStreamWaitEvent(0, evJoin, 0);

    k_spmm1<<<(N_NODES + 7) / 8, 256>>>(b1);
    k_gemm2<<<N_NODES / 32, 256>>>(W2);
    k_spmm2<<<(N_NODES + 7) / 8, 256>>>(b2, out);
}

// round 6
// speedup vs baseline: 1.7740x; 1.0117x over previous
#include <cuda_runtime.h>
#include <cuda_bf16.h>
#include <cuda_fp16.h>
#include <cstdint>

#define N_NODES 100000
#define E_MAX   1600000
#define IN_F    512
#define HID     128
#define NCLS    32

// ---------------- scratch (device globals; no allocation allowed) ------------
__device__ int    g_cnt[N_NODES];
__device__ int    g_rowstart[N_NODES];
__device__ int    g_cursor[N_NODES];
__device__ float  g_dinv[N_NODES];
__device__ int    g_col[E_MAX];
__device__ __half g_h1h[(size_t)N_NODES * HID];   // x @ W1 (fp16)
__device__ float  g_a1[(size_t)N_NODES * HID];    // relu(agg1 + b1) fp32
__device__ __half g_h2h[(size_t)N_NODES * NCLS];  // a1 @ W2 (fp16)
__device__ int    g_blocksums[128];
// W1 transposed to [N=128][K=512], split into bf16 hi/lo
__device__ __nv_bfloat16 g_whi[HID * IN_F];
__device__ __nv_bfloat16 g_wlo[HID * IN_F];

__device__ __forceinline__ uint32_t smem_u32(const void* p) {
    uint32_t a;
    asm("{ .reg .u64 t; cvta.to.shared.u64 t, %1; cvt.u32.u64 %0, t; }"
        : "=r"(a) : "l"(p));
    return a;
}

__device__ __forceinline__ void cvt_hl(float x, float y, uint32_t& h, uint32_t& l) {
    __nv_bfloat162 hb = __float22bfloat162_rn(make_float2(x, y));
    float2 bk = __bfloat1622float2(hb);
    __nv_bfloat162 lb = __float22bfloat162_rn(make_float2(x - bk.x, y - bk.y));
    h = *reinterpret_cast<uint32_t*>(&hb);
    l = *reinterpret_cast<uint32_t*>(&lb);
}

__device__ __forceinline__ void ldsm_x4(uint32_t* r, uint32_t addr) {
    asm volatile("ldmatrix.sync.aligned.m8n8.x4.shared.b16 {%0,%1,%2,%3}, [%4];"
                 : "=r"(r[0]), "=r"(r[1]), "=r"(r[2]), "=r"(r[3]) : "r"(addr));
}

__device__ __forceinline__ void mma16816(float* d, const uint32_t* a, const uint32_t* b) {
    asm volatile(
        "mma.sync.aligned.m16n8k16.row.col.f32.bf16.bf16.f32 "
        "{%0,%1,%2,%3}, {%4,%5,%6,%7}, {%8,%9}, {%0,%1,%2,%3};"
        : "+f"(d[0]), "+f"(d[1]), "+f"(d[2]), "+f"(d[3])
        : "r"(a[0]), "r"(a[1]), "r"(a[2]), "r"(a[3]), "r"(b[0]), "r"(b[1]));
}

__device__ __forceinline__ void cpasync16(uint32_t dst, const void* src) {
    size_t g = __cvta_generic_to_global(src);
    asm volatile("cp.async.cg.shared.global [%0], [%1], 16;" :: "r"(dst), "l"(g));
}

// ---------------- small helpers ------------------------------------------
__global__ void k_zero_cnt() {
    int i = blockIdx.x * blockDim.x + threadIdx.x;
    if (i < N_NODES) g_cnt[i] = 0;
}

__global__ void k_hist(const int* __restrict__ dst, int E) {
    int e = blockIdx.x * blockDim.x + threadIdx.x;
    if (e < E) atomicAdd(&g_cnt[dst[e]], 1);
}

// W1 [512][128] -> transpose + bf16 split -> g_whi/g_wlo [128][512]
__global__ void k_prepw(const float* __restrict__ W1) {
    __shared__ float sh[32][33];
    int bi = blockIdx.x & 15;        // k tile
    int bj = blockIdx.x >> 4;        // n tile
    int k0 = bi * 32, n0 = bj * 32;
    int t = threadIdx.x;
    int i = t >> 5, j = t & 31;
#pragma unroll
    for (int r = 0; r < 4; r++) {
        int kk = i + r * 8;
        sh[kk][j] = W1[(size_t)(k0 + kk) * HID + n0 + j];
    }
    __syncthreads();
#pragma unroll
    for (int r = 0; r < 4; r++) {
        int nn = i + r * 8;
        float v = sh[j][nn];
        __nv_bfloat16 h = __float2bfloat16(v);
        float rem = v - __bfloat162float(h);
        g_whi[(size_t)(n0 + nn) * IN_F + k0 + j] = h;
        g_wlo[(size_t)(n0 + nn) * IN_F + k0 + j] = __float2bfloat16(rem);
    }
}

__global__ void k_scan1() {
    __shared__ int sh[256];
    int b = blockIdx.x, t = threadIdx.x;
    int base = b * 1024 + t * 4;
    int v[4];
    int local = 0;
#pragma unroll
    for (int q = 0; q < 4; q++) {
        int i = base + q;
        v[q] = (i < N_NODES) ? g_cnt[i] : 0;
        local += v[q];
    }
    sh[t] = local;
    __syncthreads();
#pragma unroll
    for (int off = 1; off < 256; off <<= 1) {
        int add = (t >= off) ? sh[t - off] : 0;
        __syncthreads();
        sh[t] += add;
        __syncthreads();
    }
    int run = sh[t] - local;
    if (t == 255) g_blocksums[b] = sh[255];
#pragma unroll
    for (int q = 0; q < 4; q++) {
        int i = base + q;
        if (i < N_NODES) g_rowstart[i] = run;
        run += v[q];
    }
}

__global__ void k_scan2(int nblk) {
    __shared__ int sh[128];
    int t = threadIdx.x;
    int v = (t < nblk) ? g_blocksums[t] : 0;
    sh[t] = v;
    __syncthreads();
#pragma unroll
    for (int off = 1; off < 128; off <<= 1) {
        int add = (t >= off) ? sh[t - off] : 0;
        __syncthreads();
        sh[t] += add;
        __syncthreads();
    }
    if (t < nblk) g_blocksums[t] = sh[t] - v;
}

__global__ void k_scan3() {
    int i = blockIdx.x * blockDim.x + threadIdx.x;
    if (i >= N_NODES) return;
    int rs = g_rowstart[i] + g_blocksums[i >> 10];
    g_rowstart[i] = rs;
    g_cursor[i]   = rs;
    g_dinv[i]     = rsqrtf((float)(g_cnt[i] + 1));
}

__global__ void k_fill(const int* __restrict__ src, const int* __restrict__ dst, int E) {
    int e = blockIdx.x * blockDim.x + threadIdx.x;
    if (e >= E) return;
    int d = dst[e];
    int p = atomicAdd(&g_cursor[d], 1);
    g_col[p] = src[e];
}

// ---------------- GEMM1: h1 = X @ W1 via mma.sync bf16 3-pass split ----------
// BM=256, BN=128, BK=32, double-buffered. Warps: 4m x 2n; per warp mt=4, nt=8.
// Inner loop is PASS-MAJOR within each 16-col B group: 8 independent MMAs
// between accumulator reuse (breaks HMMA RAW chains).
// Stage layout (80B row stride, conflict-free):
//   Ah[256][40] 20480 | Al 20480 | Bh[128][40] 10240 | Bl 10240  = 61440
#define G1_STAGE   61440
#define G1_SMEM    (2 * G1_STAGE)

__global__ __launch_bounds__(256, 1) void k_gemm1_mma(const float* __restrict__ X) {
    extern __shared__ char smem[];
    uint32_t sb = smem_u32(smem);

    const int tid  = threadIdx.x;
    const int wid  = tid >> 5;
    const int lane = tid & 31;
    const int bm   = blockIdx.x * 256;
    const int wm   = wid & 3;    // 0..3 -> m block of 64 rows
    const int wn   = wid >> 2;   // 0..1 -> n block of 64

    int arow_g = bm + tid;
    if (arow_g >= N_NODES) arow_g = N_NODES - 1;
    const float* aptr = X + (size_t)arow_g * IN_F;

    float4 aR[8];

#define LDG_A(c) do { \
        const float4* p4 = (const float4*)(aptr + (c) * 32); \
        _Pragma("unroll") \
        for (int q = 0; q < 8; q++) aR[q] = p4[q]; \
    } while (0)

#define STS_A(s) do { \
        char* stg = smem + (s) * G1_STAGE; \
        uint4* ah4 = (uint4*)(stg + tid * 80); \
        uint4* al4 = (uint4*)(stg + 20480 + tid * 80); \
        _Pragma("unroll") \
        for (int hblk = 0; hblk < 2; hblk++) { \
            uint32_t hw[8], lw[8]; \
            _Pragma("unroll") \
            for (int q = 0; q < 4; q++) { \
                cvt_hl(aR[hblk*4+q].x, aR[hblk*4+q].y, hw[2*q],   lw[2*q]); \
                cvt_hl(aR[hblk*4+q].z, aR[hblk*4+q].w, hw[2*q+1], lw[2*q+1]); \
            } \
            _Pragma("unroll") \
            for (int j = 0; j < 2; j++) { \
                ah4[hblk*2+j] = make_uint4(hw[4*j], hw[4*j+1], hw[4*j+2], hw[4*j+3]); \
                al4[hblk*2+j] = make_uint4(lw[4*j], lw[4*j+1], lw[4*j+2], lw[4*j+3]); \
            } \
        } \
    } while (0)

#define CPA_B(c, s) do { \
        uint32_t bdst = sb + (s) * G1_STAGE + 40960; \
        _Pragma("unroll") \
        for (int q = 0; q < 2; q++) { \
            int u = tid + q * 256; \
            int row = u >> 2, j = u & 3; \
            uint32_t dh = bdst + row * 80 + j * 16; \
            cpasync16(dh, g_whi + (size_t)row * IN_F + (c) * 32 + j * 8); \
            cpasync16(dh + 10240, g_wlo + (size_t)row * IN_F + (c) * 32 + j * 8); \
        } \
        asm volatile("cp.async.commit_group;"); \
    } while (0)

    float acc[4][8][4];
#pragma unroll
    for (int m = 0; m < 4; m++)
#pragma unroll
        for (int n = 0; n < 8; n++)
#pragma unroll
            for (int q = 0; q < 4; q++) acc[m][n][q] = 0.f;

    LDG_A(0);
    STS_A(0);
    CPA_B(0, 0);
    LDG_A(1);
    asm volatile("cp.async.wait_group 0;");
    __syncthreads();

    // ldmatrix lane addressing
    const int a_row  = wm * 64 + (lane & 15);
    const int a_koff = (lane >> 4) * 8;
    const int b_n    = wn * 64 + ((lane >> 4) & 1) * 8 + (lane & 7);
    const int b_koff = ((lane >> 3) & 1) * 8;

    for (int c = 0; c < 16; c++) {
        const int s = c & 1;
        uint32_t abase = sb + s * G1_STAGE;
        uint32_t bbase = abase + 40960;

#pragma unroll
        for (int ks = 0; ks < 2; ks++) {
            uint32_t ah[4][4], al[4][4];
#pragma unroll
            for (int m = 0; m < 4; m++) {
                uint32_t ad = abase + (uint32_t)((a_row + m * 16) * 80 + (a_koff + ks * 16) * 2);
                ldsm_x4(ah[m], ad);
                ldsm_x4(al[m], ad + 20480);
            }
#pragma unroll
            for (int g = 0; g < 4; g++) {
                uint32_t bd = bbase + (uint32_t)((b_n + g * 16) * 80 + (b_koff + ks * 16) * 2);
                uint32_t rh[4], rl[4];
                ldsm_x4(rh, bd);
                ldsm_x4(rl, bd + 10240);
                // pass-major: 8 independent MMAs per pass -> acc reuse distance 8
#pragma unroll
                for (int m = 0; m < 4; m++) {
                    mma16816(acc[m][2*g],   ah[m], rh);
                    mma16816(acc[m][2*g+1], ah[m], rh + 2);
                }
#pragma unroll
                for (int m = 0; m < 4; m++) {
                    mma16816(acc[m][2*g],   ah[m], rl);
                    mma16816(acc[m][2*g+1], ah[m], rl + 2);
                }
#pragma unroll
                for (int m = 0; m < 4; m++) {
                    mma16816(acc[m][2*g],   al[m], rh);
                    mma16816(acc[m][2*g+1], al[m], rh + 2);
                }
            }
        }

        if (c < 15) {
            STS_A(s ^ 1);
            CPA_B(c + 1, s ^ 1);
            if (c < 14) LDG_A(c + 2);
            asm volatile("cp.async.wait_group 0;");
            __syncthreads();
        }
    }

    // epilogue -> fp16 h1
    const int gid = lane >> 2, tig = lane & 3;
#pragma unroll
    for (int m = 0; m < 4; m++) {
        int r0 = bm + wm * 64 + m * 16 + gid;
#pragma unroll
        for (int n = 0; n < 8; n++) {
            int col = wn * 64 + n * 8 + tig * 2;
            if (r0 < N_NODES) {
                __half2 o = __floats2half2_rn(acc[m][n][0], acc[m][n][1]);
                *(__half2*)&g_h1h[(size_t)r0 * HID + col] = o;
            }
            if (r0 + 8 < N_NODES) {
                __half2 o = __floats2half2_rn(acc[m][n][2], acc[m][n][3]);
                *(__half2*)&g_h1h[(size_t)(r0 + 8) * HID + col] = o;
            }
        }
    }
#undef LDG_A
#undef STS_A
#undef CPA_B
}

// ---------------- SpMM layer 1 (fp16 gather, fp32 acc, 4-way MLP) ------------
__global__ void k_spmm1(const float* __restrict__ b1) {
    int warp = (blockIdx.x * blockDim.x + threadIdx.x) >> 5;
    int lane = threadIdx.x & 31;
    if (warp >= N_NODES) return;
    int row   = warp;
    int start = g_rowstart[row];
    int cnt   = g_cnt[row];

    const uint2* H = reinterpret_cast<const uint2*>(g_h1h);
    const int* cp = g_col + start;
    float4 acc = make_float4(0.f, 0.f, 0.f, 0.f);

    int i = 0;
    for (; i + 4 <= cnt; i += 4) {
        int s0 = cp[i], s1 = cp[i + 1], s2 = cp[i + 2], s3 = cp[i + 3];
        float w0 = g_dinv[s0], w1 = g_dinv[s1], w2 = g_dinv[s2], w3 = g_dinv[s3];
        uint2 v0 = H[(size_t)s0 * 32 + lane];
        uint2 v1 = H[(size_t)s1 * 32 + lane];
        uint2 v2 = H[(size_t)s2 * 32 + lane];
        uint2 v3 = H[(size_t)s3 * 32 + lane];
#define ACCUM(vv, ww) do { \
            float2 f0 = __half22float2(*(__half2*)&(vv).x); \
            float2 f1 = __half22float2(*(__half2*)&(vv).y); \
            acc.x = fmaf((ww), f0.x, acc.x); \
            acc.y = fmaf((ww), f0.y, acc.y); \
            acc.z = fmaf((ww), f1.x, acc.z); \
            acc.w = fmaf((ww), f1.y, acc.w); \
        } while (0)
        ACCUM(v0, w0); ACCUM(v1, w1); ACCUM(v2, w2); ACCUM(v3, w3);
    }
    if (i + 2 <= cnt) {
        int s0 = cp[i], s1 = cp[i + 1];
        float w0 = g_dinv[s0], w1 = g_dinv[s1];
        uint2 v0 = H[(size_t)s0 * 32 + lane];
        uint2 v1 = H[(size_t)s1 * 32 + lane];
        ACCUM(v0, w0); ACCUM(v1, w1);
        i += 2;
    }
    if (i < cnt) {
        int s = cp[i];
        float w = g_dinv[s];
        uint2 v = H[(size_t)s * 32 + lane];
        ACCUM(v, w);
    }
#undef ACCUM

    float d  = g_dinv[row];
    float dd = d * d;
    uint2 hv = H[(size_t)row * 32 + lane];
    float2 s0 = __half22float2(*(__half2*)&hv.x);
    float2 s1 = __half22float2(*(__half2*)&hv.y);
    float4 bb = reinterpret_cast<const float4*>(b1)[lane];
    float4 r;
    r.x = fmaxf(fmaf(d, acc.x, dd * s0.x) + bb.x, 0.f);
    r.y = fmaxf(fmaf(d, acc.y, dd * s0.y) + bb.y, 0.f);
    r.z = fmaxf(fmaf(d, acc.z, dd * s1.x) + bb.z, 0.f);
    r.w = fmaxf(fmaf(d, acc.w, dd * s1.y) + bb.w, 0.f);
    reinterpret_cast<float4*>(g_a1)[(size_t)row * 32 + lane] = r;
}

// ---------------- GEMM2: h2[N,32] = a1[N,128] @ W2[128,32] -------------------
__global__ __launch_bounds__(256) void k_gemm2(const float* __restrict__ W2) {
    __shared__ float As[32 * 132];
    __shared__ float Ws[128 * 32];

    int t    = threadIdx.x;
    int row0 = blockIdx.x * 32;

#pragma unroll
    for (int q = 0; q < 4; q++) {
        int f4 = t + 256 * q;
        *reinterpret_cast<float4*>(&Ws[f4 * 4]) =
            *reinterpret_cast<const float4*>(&W2[f4 * 4]);
        int r  = f4 >> 5;
        int c4 = f4 & 31;
        float4 av = *reinterpret_cast<const float4*>(
            &g_a1[(size_t)(row0 + r) * HID + c4 * 4]);
        *reinterpret_cast<float4*>(&As[r * 132 + c4 * 4]) = av;
    }
    __syncthreads();

    int r  = t >> 3;
    int cg = t & 7;
    float4 acc = make_float4(0.f, 0.f, 0.f, 0.f);
#pragma unroll 4
    for (int k = 0; k < HID; k += 4) {
        float4 a4 = *reinterpret_cast<const float4*>(&As[r * 132 + k]);
        float am[4] = {a4.x, a4.y, a4.z, a4.w};
#pragma unroll
        for (int kk = 0; kk < 4; kk++) {
            float4 w = *reinterpret_cast<const float4*>(&Ws[(k + kk) * 32 + cg * 4]);
            acc.x = fmaf(am[kk], w.x, acc.x);
            acc.y = fmaf(am[kk], w.y, acc.y);
            acc.z = fmaf(am[kk], w.z, acc.z);
            acc.w = fmaf(am[kk], w.w, acc.w);
        }
    }
    __half2 o0 = __floats2half2_rn(acc.x, acc.y);
    __half2 o1 = __floats2half2_rn(acc.z, acc.w);
    uint2 ov = make_uint2(*(uint32_t*)&o0, *(uint32_t*)&o1);
    *reinterpret_cast<uint2*>(&g_h2h[(size_t)(row0 + r) * NCLS + cg * 4]) = ov;
}

// ---------------- SpMM layer 2 (fp16 gather, 4-way MLP) -----------------------
__global__ void k_spmm2(const float* __restrict__ b2, float* __restrict__ out) {
    int warp = (blockIdx.x * blockDim.x + threadIdx.x) >> 5;
    int lane = threadIdx.x & 31;
    if (warp >= N_NODES) return;
    int row   = warp;
    int start = g_rowstart[row];
    int cnt   = g_cnt[row];
    const int* cp = g_col + start;

    float acc = 0.f;
    int i = 0;
    for (; i + 4 <= cnt; i += 4) {
        int s0 = cp[i], s1 = cp[i + 1], s2 = cp[i + 2], s3 = cp[i + 3];
        float w0 = g_dinv[s0], w1 = g_dinv[s1], w2 = g_dinv[s2], w3 = g_dinv[s3];
        float v0 = __half2float(g_h2h[(size_t)s0 * NCLS + lane]);
        float v1 = __half2float(g_h2h[(size_t)s1 * NCLS + lane]);
        float v2 = __half2float(g_h2h[(size_t)s2 * NCLS + lane]);
        float v3 = __half2float(g_h2h[(size_t)s3 * NCLS + lane]);
        acc = fmaf(w0, v0, acc);
        acc = fmaf(w1, v1, acc);
        acc = fmaf(w2, v2, acc);
        acc = fmaf(w3, v3, acc);
    }
    for (; i < cnt; i++) {
        int s = cp[i];
        acc = fmaf(g_dinv[s], __half2float(g_h2h[(size_t)s * NCLS + lane]), acc);
    }
    float d = g_dinv[row];
    float self = __half2float(g_h2h[(size_t)row * NCLS + lane]);
    out[(size_t)row * NCLS + lane] = fmaf(d, acc, d * d * self) + b2[lane];
}

// ---------------- launch ------------------------------------------------------
extern "C" void kernel_launch(void* const* d_in, const int* in_sizes, int n_in,
                              void* d_out, int out_size) {
    const float* x  = (const float*)d_in[0];
    const int*   ei = (const int*)d_in[1];
    const float* W1 = (const float*)d_in[2];
    const float* b1 = (const float*)d_in[3];
    const float* W2 = (const float*)d_in[4];
    const float* b2 = (const float*)d_in[5];
    float* out = (float*)d_out;

    int E = in_sizes[1] / 2;
    const int* src = ei;
    const int* dst = ei + E;

    int nScanBlocks = (N_NODES + 1023) / 1024;   // 98

    static cudaStream_t s2 = nullptr;
    static cudaEvent_t evFork = nullptr, evJoin = nullptr;
    static bool init_done = false;
    if (!init_done) {
        cudaFuncSetAttribute(k_gemm1_mma,
                             cudaFuncAttributeMaxDynamicSharedMemorySize,
                             G1_SMEM);
        cudaStreamCreateWithFlags(&s2, cudaStreamNonBlocking);
        cudaEventCreateWithFlags(&evFork, cudaEventDisableTiming);
        cudaEventCreateWithFlags(&evJoin, cudaEventDisableTiming);
        init_done = true;
    }

    // fork: CSR build on s2, GEMM path on the main (captured) stream
    cudaEventRecord(evFork, 0);
    cudaStreamWaitEvent(s2, evFork, 0);

    k_zero_cnt<<<(N_NODES + 255) / 256, 256, 0, s2>>>();
    k_hist<<<(E + 255) / 256, 256, 0, s2>>>(dst, E);
    k_scan1<<<nScanBlocks, 256, 0, s2>>>();
    k_scan2<<<1, 128, 0, s2>>>(nScanBlocks);
    k_scan3<<<(N_NODES + 255) / 256, 256, 0, s2>>>();
    k_fill<<<(E + 255) / 256, 256, 0, s2>>>(src, dst, E);
    cudaEventRecord(evJoin, s2);

    k_prepw<<<64, 256>>>(W1);
    k_gemm1_mma<<<(N_NODES + 255) / 256, 256, G1_SMEM>>>(x);

    // join
    cudaStreamWaitEvent(0, evJoin, 0);

    k_spmm1<<<(N_NODES + 7) / 8, 256>>>(b1);
    k_gemm2<<<N_NODES / 32, 256>>>(W2);
    k_spmm2<<<(N_NODES + 7) / 8, 256>>>(b2, out);
}

// round 7
// speedup vs baseline: 1.8358x; 1.0348x over previous
#include <cuda_runtime.h>
#include <cuda_bf16.h>
#include <cuda_fp16.h>
#include <cstdint>

#define N_NODES 100000
#define E_MAX   1600000
#define IN_F    512
#define HID     128
#define NCLS    32

// ---------------- scratch (device globals; no allocation allowed) ------------
__device__ int    g_cnt[N_NODES];
__device__ int    g_rowstart[N_NODES];
__device__ int    g_cursor[N_NODES];
__device__ float  g_dinv[N_NODES];
__device__ int    g_col[E_MAX];
__device__ __half g_h1h[(size_t)N_NODES * HID];   // x @ W1 (fp16)
__device__ float  g_a1[(size_t)N_NODES * HID];    // relu(agg1 + b1) fp32
__device__ __half g_h2h[(size_t)N_NODES * NCLS];  // a1 @ W2 (fp16)
__device__ int    g_blocksums[128];
// W1 transposed to [N=128][K=512], split into bf16 hi/lo
__device__ __nv_bfloat16 g_whi[HID * IN_F];
__device__ __nv_bfloat16 g_wlo[HID * IN_F];

__device__ __forceinline__ uint32_t smem_u32(const void* p) {
    uint32_t a;
    asm("{ .reg .u64 t; cvta.to.shared.u64 t, %1; cvt.u32.u64 %0, t; }"
        : "=r"(a) : "l"(p));
    return a;
}

__device__ __forceinline__ void cvt_hl(float x, float y, uint32_t& h, uint32_t& l) {
    __nv_bfloat162 hb = __float22bfloat162_rn(make_float2(x, y));
    float2 bk = __bfloat1622float2(hb);
    __nv_bfloat162 lb = __float22bfloat162_rn(make_float2(x - bk.x, y - bk.y));
    h = *reinterpret_cast<uint32_t*>(&hb);
    l = *reinterpret_cast<uint32_t*>(&lb);
}

__device__ __forceinline__ void ldsm_x4(uint32_t* r, uint32_t addr) {
    asm volatile("ldmatrix.sync.aligned.m8n8.x4.shared.b16 {%0,%1,%2,%3}, [%4];"
                 : "=r"(r[0]), "=r"(r[1]), "=r"(r[2]), "=r"(r[3]) : "r"(addr));
}

__device__ __forceinline__ void mma16816(float* d, const uint32_t* a, const uint32_t* b) {
    asm volatile(
        "mma.sync.aligned.m16n8k16.row.col.f32.bf16.bf16.f32 "
        "{%0,%1,%2,%3}, {%4,%5,%6,%7}, {%8,%9}, {%0,%1,%2,%3};"
        : "+f"(d[0]), "+f"(d[1]), "+f"(d[2]), "+f"(d[3])
        : "r"(a[0]), "r"(a[1]), "r"(a[2]), "r"(a[3]), "r"(b[0]), "r"(b[1]));
}

__device__ __forceinline__ void cpasync16(uint32_t dst, const void* src) {
    size_t g = __cvta_generic_to_global(src);
    asm volatile("cp.async.cg.shared.global [%0], [%1], 16;" :: "r"(dst), "l"(g));
}

// ---------------- small helpers ------------------------------------------
__global__ void k_zero_cnt() {
    int i = blockIdx.x * blockDim.x + threadIdx.x;
    if (i < N_NODES) g_cnt[i] = 0;
}

__global__ void k_hist(const int* __restrict__ dst, int E) {
    int e = blockIdx.x * blockDim.x + threadIdx.x;
    if (e < E) atomicAdd(&g_cnt[dst[e]], 1);
}

// W1 [512][128] -> transpose + bf16 split -> g_whi/g_wlo [128][512]
__global__ void k_prepw(const float* __restrict__ W1) {
    __shared__ float sh[32][33];
    int bi = blockIdx.x & 15;        // k tile
    int bj = blockIdx.x >> 4;        // n tile
    int k0 = bi * 32, n0 = bj * 32;
    int t = threadIdx.x;
    int i = t >> 5, j = t & 31;
#pragma unroll
    for (int r = 0; r < 4; r++) {
        int kk = i + r * 8;
        sh[kk][j] = W1[(size_t)(k0 + kk) * HID + n0 + j];
    }
    __syncthreads();
#pragma unroll
    for (int r = 0; r < 4; r++) {
        int nn = i + r * 8;
        float v = sh[j][nn];
        __nv_bfloat16 h = __float2bfloat16(v);
        float rem = v - __bfloat162float(h);
        g_whi[(size_t)(n0 + nn) * IN_F + k0 + j] = h;
        g_wlo[(size_t)(n0 + nn) * IN_F + k0 + j] = __float2bfloat16(rem);
    }
}

__global__ void k_scan1() {
    __shared__ int sh[256];
    int b = blockIdx.x, t = threadIdx.x;
    int base = b * 1024 + t * 4;
    int v[4];
    int local = 0;
#pragma unroll
    for (int q = 0; q < 4; q++) {
        int i = base + q;
        v[q] = (i < N_NODES) ? g_cnt[i] : 0;
        local += v[q];
    }
    sh[t] = local;
    __syncthreads();
#pragma unroll
    for (int off = 1; off < 256; off <<= 1) {
        int add = (t >= off) ? sh[t - off] : 0;
        __syncthreads();
        sh[t] += add;
        __syncthreads();
    }
    int run = sh[t] - local;
    if (t == 255) g_blocksums[b] = sh[255];
#pragma unroll
    for (int q = 0; q < 4; q++) {
        int i = base + q;
        if (i < N_NODES) g_rowstart[i] = run;
        run += v[q];
    }
}

__global__ void k_scan2(int nblk) {
    __shared__ int sh[128];
    int t = threadIdx.x;
    int v = (t < nblk) ? g_blocksums[t] : 0;
    sh[t] = v;
    __syncthreads();
#pragma unroll
    for (int off = 1; off < 128; off <<= 1) {
        int add = (t >= off) ? sh[t - off] : 0;
        __syncthreads();
        sh[t] += add;
        __syncthreads();
    }
    if (t < nblk) g_blocksums[t] = sh[t] - v;
}

__global__ void k_scan3() {
    int i = blockIdx.x * blockDim.x + threadIdx.x;
    if (i >= N_NODES) return;
    int rs = g_rowstart[i] + g_blocksums[i >> 10];
    g_rowstart[i] = rs;
    g_cursor[i]   = rs;
    g_dinv[i]     = rsqrtf((float)(g_cnt[i] + 1));
}

__global__ void k_fill(const int* __restrict__ src, const int* __restrict__ dst, int E) {
    int e = blockIdx.x * blockDim.x + threadIdx.x;
    if (e >= E) return;
    int d = dst[e];
    int p = atomicAdd(&g_cursor[d], 1);
    g_col[p] = src[e];
}

// ---------------- GEMM1: h1 = X @ W1 via mma.sync bf16 3-pass split ----------
// BM=128, BN=128, BK=32, double-buffered, 2 CTAs/SM (16 warps) for latency
// hiding. Warps 4m x 2n; per warp mt=2, nt=8 (64 acc regs/thread).
// Stage layout (80B row stride, conflict-free):
//   Ah[128][40] 10240 | Al 10240 | Bh[128][40] 10240 | Bl 10240  = 40960
#define G1_STAGE   40960
#define G1_SMEM    (2 * G1_STAGE)

__global__ __launch_bounds__(256, 2) void k_gemm1_mma(const float* __restrict__ X) {
    extern __shared__ char smem[];
    uint32_t sb = smem_u32(smem);

    const int tid  = threadIdx.x;
    const int wid  = tid >> 5;
    const int lane = tid & 31;
    const int bm   = blockIdx.x * 128;
    const int wm   = wid & 3;    // 0..3 -> m block of 32 rows
    const int wn   = wid >> 2;   // 0..1 -> n block of 64

    // A global load: 2 threads per row, 16 floats each per k32 chunk
    const int arow_l = tid >> 1;          // 0..127
    const int ahalf  = tid & 1;
    int arow_g = bm + arow_l;
    if (arow_g >= N_NODES) arow_g = N_NODES - 1;
    const float* aptr = X + (size_t)arow_g * IN_F + ahalf * 16;

    float4 aR[4];

#define LDG_A(c) do { \
        const float4* p4 = (const float4*)(aptr + (c) * 32); \
        _Pragma("unroll") \
        for (int q = 0; q < 4; q++) aR[q] = p4[q]; \
    } while (0)

#define STS_A(s) do { \
        char* stg = smem + (s) * G1_STAGE; \
        uint32_t hw[8], lw[8]; \
        _Pragma("unroll") \
        for (int q = 0; q < 4; q++) { \
            cvt_hl(aR[q].x, aR[q].y, hw[2*q],   lw[2*q]); \
            cvt_hl(aR[q].z, aR[q].w, hw[2*q+1], lw[2*q+1]); \
        } \
        uint4* ah4 = (uint4*)(stg + arow_l * 80 + ahalf * 32); \
        uint4* al4 = (uint4*)(stg + 10240 + arow_l * 80 + ahalf * 32); \
        ah4[0] = make_uint4(hw[0], hw[1], hw[2], hw[3]); \
        ah4[1] = make_uint4(hw[4], hw[5], hw[6], hw[7]); \
        al4[0] = make_uint4(lw[0], lw[1], lw[2], lw[3]); \
        al4[1] = make_uint4(lw[4], lw[5], lw[6], lw[7]); \
    } while (0)

#define CPA_B(c, s) do { \
        uint32_t bdst = sb + (s) * G1_STAGE + 20480; \
        _Pragma("unroll") \
        for (int q = 0; q < 2; q++) { \
            int u = tid + q * 256; \
            int row = u >> 2, j = u & 3; \
            uint32_t dh = bdst + row * 80 + j * 16; \
            cpasync16(dh, g_whi + (size_t)row * IN_F + (c) * 32 + j * 8); \
            cpasync16(dh + 10240, g_wlo + (size_t)row * IN_F + (c) * 32 + j * 8); \
        } \
        asm volatile("cp.async.commit_group;"); \
    } while (0)

    float acc[2][8][4];
#pragma unroll
    for (int m = 0; m < 2; m++)
#pragma unroll
        for (int n = 0; n < 8; n++)
#pragma unroll
            for (int q = 0; q < 4; q++) acc[m][n][q] = 0.f;

    LDG_A(0);
    STS_A(0);
    CPA_B(0, 0);
    LDG_A(1);
    asm volatile("cp.async.wait_group 0;");
    __syncthreads();

    // ldmatrix lane addressing
    const int a_row  = wm * 32 + (lane & 15);
    const int a_koff = (lane >> 4) * 8;
    const int b_n    = wn * 64 + ((lane >> 4) & 1) * 8 + (lane & 7);
    const int b_koff = ((lane >> 3) & 1) * 8;

    for (int c = 0; c < 16; c++) {
        const int s = c & 1;
        uint32_t abase = sb + s * G1_STAGE;
        uint32_t bbase = abase + 20480;

#pragma unroll
        for (int ks = 0; ks < 2; ks++) {
            uint32_t ah[2][4], al[2][4];
#pragma unroll
            for (int m = 0; m < 2; m++) {
                uint32_t ad = abase + (uint32_t)((a_row + m * 16) * 80 + (a_koff + ks * 16) * 2);
                ldsm_x4(ah[m], ad);
                ldsm_x4(al[m], ad + 10240);
            }
#pragma unroll
            for (int g = 0; g < 4; g++) {
                uint32_t bd = bbase + (uint32_t)((b_n + g * 16) * 80 + (b_koff + ks * 16) * 2);
                uint32_t rh[4], rl[4];
                ldsm_x4(rh, bd);
                ldsm_x4(rl, bd + 10240);
#pragma unroll
                for (int m = 0; m < 2; m++) {
                    mma16816(acc[m][2*g],   ah[m], rh);
                    mma16816(acc[m][2*g+1], ah[m], rh + 2);
                }
#pragma unroll
                for (int m = 0; m < 2; m++) {
                    mma16816(acc[m][2*g],   ah[m], rl);
                    mma16816(acc[m][2*g+1], ah[m], rl + 2);
                }
#pragma unroll
                for (int m = 0; m < 2; m++) {
                    mma16816(acc[m][2*g],   al[m], rh);
                    mma16816(acc[m][2*g+1], al[m], rh + 2);
                }
            }
        }

        if (c < 15) {
            STS_A(s ^ 1);
            CPA_B(c + 1, s ^ 1);
            if (c < 14) LDG_A(c + 2);
            asm volatile("cp.async.wait_group 0;");
            __syncthreads();
        }
    }

    // epilogue -> fp16 h1
    const int gid = lane >> 2, tig = lane & 3;
#pragma unroll
    for (int m = 0; m < 2; m++) {
        int r0 = bm + wm * 32 + m * 16 + gid;
#pragma unroll
        for (int n = 0; n < 8; n++) {
            int col = wn * 64 + n * 8 + tig * 2;
            if (r0 < N_NODES) {
                __half2 o = __floats2half2_rn(acc[m][n][0], acc[m][n][1]);
                *(__half2*)&g_h1h[(size_t)r0 * HID + col] = o;
            }
            if (r0 + 8 < N_NODES) {
                __half2 o = __floats2half2_rn(acc[m][n][2], acc[m][n][3]);
                *(__half2*)&g_h1h[(size_t)(r0 + 8) * HID + col] = o;
            }
        }
    }
#undef LDG_A
#undef STS_A
#undef CPA_B
}

// ---------------- SpMM layer 1 (fp16 gather, fp32 acc, 4-way MLP) ------------
__global__ void k_spmm1(const float* __restrict__ b1) {
    int warp = (blockIdx.x * blockDim.x + threadIdx.x) >> 5;
    int lane = threadIdx.x & 31;
    if (warp >= N_NODES) return;
    int row   = warp;
    int start = g_rowstart[row];
    int cnt   = g_cnt[row];

    const uint2* H = reinterpret_cast<const uint2*>(g_h1h);
    const int* cp = g_col + start;
    float4 acc = make_float4(0.f, 0.f, 0.f, 0.f);

    int i = 0;
    for (; i + 4 <= cnt; i += 4) {
        int s0 = cp[i], s1 = cp[i + 1], s2 = cp[i + 2], s3 = cp[i + 3];
        float w0 = g_dinv[s0], w1 = g_dinv[s1], w2 = g_dinv[s2], w3 = g_dinv[s3];
        uint2 v0 = H[(size_t)s0 * 32 + lane];
        uint2 v1 = H[(size_t)s1 * 32 + lane];
        uint2 v2 = H[(size_t)s2 * 32 + lane];
        uint2 v3 = H[(size_t)s3 * 32 + lane];
#define ACCUM(vv, ww) do { \
            float2 f0 = __half22float2(*(__half2*)&(vv).x); \
            float2 f1 = __half22float2(*(__half2*)&(vv).y); \
            acc.x = fmaf((ww), f0.x, acc.x); \
            acc.y = fmaf((ww), f0.y, acc.y); \
            acc.z = fmaf((ww), f1.x, acc.z); \
            acc.w = fmaf((ww), f1.y, acc.w); \
        } while (0)
        ACCUM(v0, w0); ACCUM(v1, w1); ACCUM(v2, w2); ACCUM(v3, w3);
    }
    if (i + 2 <= cnt) {
        int s0 = cp[i], s1 = cp[i + 1];
        float w0 = g_dinv[s0], w1 = g_dinv[s1];
        uint2 v0 = H[(size_t)s0 * 32 + lane];
        uint2 v1 = H[(size_t)s1 * 32 + lane];
        ACCUM(v0, w0); ACCUM(v1, w1);
        i += 2;
    }
    if (i < cnt) {
        int s = cp[i];
        float w = g_dinv[s];
        uint2 v = H[(size_t)s * 32 + lane];
        ACCUM(v, w);
    }
#undef ACCUM

    float d  = g_dinv[row];
    float dd = d * d;
    uint2 hv = H[(size_t)row * 32 + lane];
    float2 s0 = __half22float2(*(__half2*)&hv.x);
    float2 s1 = __half22float2(*(__half2*)&hv.y);
    float4 bb = reinterpret_cast<const float4*>(b1)[lane];
    float4 r;
    r.x = fmaxf(fmaf(d, acc.x, dd * s0.x) + bb.x, 0.f);
    r.y = fmaxf(fmaf(d, acc.y, dd * s0.y) + bb.y, 0.f);
    r.z = fmaxf(fmaf(d, acc.z, dd * s1.x) + bb.z, 0.f);
    r.w = fmaxf(fmaf(d, acc.w, dd * s1.y) + bb.w, 0.f);
    reinterpret_cast<float4*>(g_a1)[(size_t)row * 32 + lane] = r;
}

// ---------------- GEMM2: h2[N,32] = a1[N,128] @ W2[128,32] -------------------
__global__ __launch_bounds__(256) void k_gemm2(const float* __restrict__ W2) {
    __shared__ float As[32 * 132];
    __shared__ float Ws[128 * 32];

    int t    = threadIdx.x;
    int row0 = blockIdx.x * 32;

#pragma unroll
    for (int q = 0; q < 4; q++) {
        int f4 = t + 256 * q;
        *reinterpret_cast<float4*>(&Ws[f4 * 4]) =
            *reinterpret_cast<const float4*>(&W2[f4 * 4]);
        int r  = f4 >> 5;
        int c4 = f4 & 31;
        float4 av = *reinterpret_cast<const float4*>(
            &g_a1[(size_t)(row0 + r) * HID + c4 * 4]);
        *reinterpret_cast<float4*>(&As[r * 132 + c4 * 4]) = av;
    }
    __syncthreads();

    int r  = t >> 3;
    int cg = t & 7;
    float4 acc = make_float4(0.f, 0.f, 0.f, 0.f);
#pragma unroll 4
    for (int k = 0; k < HID; k += 4) {
        float4 a4 = *reinterpret_cast<const float4*>(&As[r * 132 + k]);
        float am[4] = {a4.x, a4.y, a4.z, a4.w};
#pragma unroll
        for (int kk = 0; kk < 4; kk++) {
            float4 w = *reinterpret_cast<const float4*>(&Ws[(k + kk) * 32 + cg * 4]);
            acc.x = fmaf(am[kk], w.x, acc.x);
            acc.y = fmaf(am[kk], w.y, acc.y);
            acc.z = fmaf(am[kk], w.z, acc.z);
            acc.w = fmaf(am[kk], w.w, acc.w);
        }
    }
    __half2 o0 = __floats2half2_rn(acc.x, acc.y);
    __half2 o1 = __floats2half2_rn(acc.z, acc.w);
    uint2 ov = make_uint2(*(uint32_t*)&o0, *(uint32_t*)&o1);
    *reinterpret_cast<uint2*>(&g_h2h[(size_t)(row0 + r) * NCLS + cg * 4]) = ov;
}

// ---------------- SpMM layer 2 (fp16 gather, 4-way MLP) -----------------------
__global__ void k_spmm2(const float* __restrict__ b2, float* __restrict__ out) {
    int warp = (blockIdx.x * blockDim.x + threadIdx.x) >> 5;
    int lane = threadIdx.x & 31;
    if (warp >= N_NODES) return;
    int row   = warp;
    int start = g_rowstart[row];
    int cnt   = g_cnt[row];
    const int* cp = g_col + start;

    float acc = 0.f;
    int i = 0;
    for (; i + 4 <= cnt; i += 4) {
        int s0 = cp[i], s1 = cp[i + 1], s2 = cp[i + 2], s3 = cp[i + 3];
        float w0 = g_dinv[s0], w1 = g_dinv[s1], w2 = g_dinv[s2], w3 = g_dinv[s3];
        float v0 = __half2float(g_h2h[(size_t)s0 * NCLS + lane]);
        float v1 = __half2float(g_h2h[(size_t)s1 * NCLS + lane]);
        float v2 = __half2float(g_h2h[(size_t)s2 * NCLS + lane]);
        float v3 = __half2float(g_h2h[(size_t)s3 * NCLS + lane]);
        acc = fmaf(w0, v0, acc);
        acc = fmaf(w1, v1, acc);
        acc = fmaf(w2, v2, acc);
        acc = fmaf(w3, v3, acc);
    }
    for (; i < cnt; i++) {
        int s = cp[i];
        acc = fmaf(g_dinv[s], __half2float(g_h2h[(size_t)s * NCLS + lane]), acc);
    }
    float d = g_dinv[row];
    float self = __half2float(g_h2h[(size_t)row * NCLS + lane]);
    out[(size_t)row * NCLS + lane] = fmaf(d, acc, d * d * self) + b2[lane];
}

// ---------------- launch ------------------------------------------------------
extern "C" void kernel_launch(void* const* d_in, const int* in_sizes, int n_in,
                              void* d_out, int out_size) {
    const float* x  = (const float*)d_in[0];
    const int*   ei = (const int*)d_in[1];
    const float* W1 = (const float*)d_in[2];
    const float* b1 = (const float*)d_in[3];
    const float* W2 = (const float*)d_in[4];
    const float* b2 = (const float*)d_in[5];
    float* out = (float*)d_out;

    int E = in_sizes[1] / 2;
    const int* src = ei;
    const int* dst = ei + E;

    int nScanBlocks = (N_NODES + 1023) / 1024;   // 98

    static cudaStream_t s2 = nullptr;
    static cudaEvent_t evFork = nullptr, evJoin = nullptr;
    static bool init_done = false;
    if (!init_done) {
        cudaFuncSetAttribute(k_gemm1_mma,
                             cudaFuncAttributeMaxDynamicSharedMemorySize,
                             G1_SMEM);
        cudaStreamCreateWithFlags(&s2, cudaStreamNonBlocking);
        cudaEventCreateWithFlags(&evFork, cudaEventDisableTiming);
        cudaEventCreateWithFlags(&evJoin, cudaEventDisableTiming);
        init_done = true;
    }

    // fork: CSR build on s2, GEMM path on the main (captured) stream
    cudaEventRecord(evFork, 0);
    cudaStreamWaitEvent(s2, evFork, 0);

    k_zero_cnt<<<(N_NODES + 255) / 256, 256, 0, s2>>>();
    k_hist<<<(E + 255) / 256, 256, 0, s2>>>(dst, E);
    k_scan1<<<nScanBlocks, 256, 0, s2>>>();
    k_scan2<<<1, 128, 0, s2>>>(nScanBlocks);
    k_scan3<<<(N_NODES + 255) / 256, 256, 0, s2>>>();
    k_fill<<<(E + 255) / 256, 256, 0, s2>>>(src, dst, E);
    cudaEventRecord(evJoin, s2);

    k_prepw<<<64, 256>>>(W1);
    k_gemm1_mma<<<(N_NODES + 127) / 128, 256, G1_SMEM>>>(x);

    // join
    cudaStreamWaitEvent(0, evJoin, 0);

    k_spmm1<<<(N_NODES + 7) / 8, 256>>>(b1);
    k_gemm2<<<N_NODES / 32, 256>>>(W2);
    k_spmm2<<<(N_NODES + 7) / 8, 256>>>(b2, out);
}

// round 8
// speedup vs baseline: 2.0932x; 1.1402x over previous
#include <cuda_runtime.h>
#include <cuda_fp16.h>
#include <cstdint>

#define N_NODES 100000
#define E_MAX   1600000
#define IN_F    512
#define HID     128
#define NCLS    32

// ---------------- scratch (device globals; no allocation allowed) ------------
__device__ int    g_cnt[N_NODES];
__device__ int    g_rowstart[N_NODES];
__device__ int    g_cursor[N_NODES];
__device__ float  g_dinv[N_NODES];
__device__ int    g_col[E_MAX];
__device__ __half g_h1h[(size_t)N_NODES * HID];   // x @ W1 (fp16)
__device__ float  g_a1[(size_t)N_NODES * HID];    // relu(agg1 + b1) fp32
__device__ __half g_h2h[(size_t)N_NODES * NCLS];  // a1 @ W2 (fp16)
__device__ int    g_blocksums[128];
// W1 transposed to [N=128][K=512], fp16
__device__ __half g_wh[HID * IN_F];

__device__ __forceinline__ uint32_t smem_u32(const void* p) {
    uint32_t a;
    asm("{ .reg .u64 t; cvta.to.shared.u64 t, %1; cvt.u32.u64 %0, t; }"
        : "=r"(a) : "l"(p));
    return a;
}

__device__ __forceinline__ void ldsm_x4(uint32_t* r, uint32_t addr) {
    asm volatile("ldmatrix.sync.aligned.m8n8.x4.shared.b16 {%0,%1,%2,%3}, [%4];"
                 : "=r"(r[0]), "=r"(r[1]), "=r"(r[2]), "=r"(r[3]) : "r"(addr));
}

__device__ __forceinline__ void mma16816(float* d, const uint32_t* a, const uint32_t* b) {
    asm volatile(
        "mma.sync.aligned.m16n8k16.row.col.f32.f16.f16.f32 "
        "{%0,%1,%2,%3}, {%4,%5,%6,%7}, {%8,%9}, {%0,%1,%2,%3};"
        : "+f"(d[0]), "+f"(d[1]), "+f"(d[2]), "+f"(d[3])
        : "r"(a[0]), "r"(a[1]), "r"(a[2]), "r"(a[3]), "r"(b[0]), "r"(b[1]));
}

__device__ __forceinline__ void cpasync16(uint32_t dst, const void* src) {
    size_t g = __cvta_generic_to_global(src);
    asm volatile("cp.async.cg.shared.global [%0], [%1], 16;" :: "r"(dst), "l"(g));
}

// ---------------- small helpers ------------------------------------------
__global__ void k_zero_cnt() {
    int i = blockIdx.x * blockDim.x + threadIdx.x;
    if (i < N_NODES) g_cnt[i] = 0;
}

__global__ void k_hist(const int* __restrict__ dst, int E) {
    int e = blockIdx.x * blockDim.x + threadIdx.x;
    if (e < E) atomicAdd(&g_cnt[dst[e]], 1);
}

// W1 [512][128] -> transpose + fp16 -> g_wh [128][512]
__global__ void k_prepw(const float* __restrict__ W1) {
    __shared__ float sh[32][33];
    int bi = blockIdx.x & 15;        // k tile
    int bj = blockIdx.x >> 4;        // n tile
    int k0 = bi * 32, n0 = bj * 32;
    int t = threadIdx.x;
    int i = t >> 5, j = t & 31;
#pragma unroll
    for (int r = 0; r < 4; r++) {
        int kk = i + r * 8;
        sh[kk][j] = W1[(size_t)(k0 + kk) * HID + n0 + j];
    }
    __syncthreads();
#pragma unroll
    for (int r = 0; r < 4; r++) {
        int nn = i + r * 8;
        g_wh[(size_t)(n0 + nn) * IN_F + k0 + j] = __float2half_rn(sh[j][nn]);
    }
}

__global__ void k_scan1() {
    __shared__ int sh[256];
    int b = blockIdx.x, t = threadIdx.x;
    int base = b * 1024 + t * 4;
    int v[4];
    int local = 0;
#pragma unroll
    for (int q = 0; q < 4; q++) {
        int i = base + q;
        v[q] = (i < N_NODES) ? g_cnt[i] : 0;
        local += v[q];
    }
    sh[t] = local;
    __syncthreads();
#pragma unroll
    for (int off = 1; off < 256; off <<= 1) {
        int add = (t >= off) ? sh[t - off] : 0;
        __syncthreads();
        sh[t] += add;
        __syncthreads();
    }
    int run = sh[t] - local;
    if (t == 255) g_blocksums[b] = sh[255];
#pragma unroll
    for (int q = 0; q < 4; q++) {
        int i = base + q;
        if (i < N_NODES) g_rowstart[i] = run;
        run += v[q];
    }
}

__global__ void k_scan2(int nblk) {
    __shared__ int sh[128];
    int t = threadIdx.x;
    int v = (t < nblk) ? g_blocksums[t] : 0;
    sh[t] = v;
    __syncthreads();
#pragma unroll
    for (int off = 1; off < 128; off <<= 1) {
        int add = (t >= off) ? sh[t - off] : 0;
        __syncthreads();
        sh[t] += add;
        __syncthreads();
    }
    if (t < nblk) g_blocksums[t] = sh[t] - v;
}

__global__ void k_scan3() {
    int i = blockIdx.x * blockDim.x + threadIdx.x;
    if (i >= N_NODES) return;
    int rs = g_rowstart[i] + g_blocksums[i >> 10];
    g_rowstart[i] = rs;
    g_cursor[i]   = rs;
    g_dinv[i]     = rsqrtf((float)(g_cnt[i] + 1));
}

__global__ void k_fill(const int* __restrict__ src, const int* __restrict__ dst, int E) {
    int e = blockIdx.x * blockDim.x + threadIdx.x;
    if (e >= E) return;
    int d = dst[e];
    int p = atomicAdd(&g_cursor[d], 1);
    g_col[p] = src[e];
}

// ---------------- GEMM1: h1 = X @ W1, single-pass fp16 mma -------------------
// BM=128, BN=128, BK=32, double-buffered, 2 CTAs/SM.
// Warps 4m x 2n; per warp mt=2, nt=8 (64 acc regs/thread).
// Stage layout (80B row stride = 32 halfs data + pad, conflict-free):
//   A[128][80B] 10240 | B[128][80B] 10240  = 20480
#define G1_STAGE   20480
#define G1_SMEM    (2 * G1_STAGE)

__global__ __launch_bounds__(256, 2) void k_gemm1_mma(const float* __restrict__ X) {
    extern __shared__ char smem[];
    uint32_t sb = smem_u32(smem);

    const int tid  = threadIdx.x;
    const int wid  = tid >> 5;
    const int lane = tid & 31;
    const int bm   = blockIdx.x * 128;
    const int wm   = wid & 3;    // 0..3 -> m block of 32 rows
    const int wn   = wid >> 2;   // 0..1 -> n block of 64

    // A global load: 2 threads per row, 16 floats each per k32 chunk
    const int arow_l = tid >> 1;          // 0..127
    const int ahalf  = tid & 1;
    int arow_g = bm + arow_l;
    if (arow_g >= N_NODES) arow_g = N_NODES - 1;
    const float* aptr = X + (size_t)arow_g * IN_F + ahalf * 16;

    float4 aR[4];

#define LDG_A(c) do { \
        const float4* p4 = (const float4*)(aptr + (c) * 32); \
        _Pragma("unroll") \
        for (int q = 0; q < 4; q++) aR[q] = p4[q]; \
    } while (0)

#define STS_A(s) do { \
        char* stg = smem + (s) * G1_STAGE; \
        uint32_t hw[8]; \
        _Pragma("unroll") \
        for (int q = 0; q < 4; q++) { \
            __half2 p0 = __float22half2_rn(make_float2(aR[q].x, aR[q].y)); \
            __half2 p1 = __float22half2_rn(make_float2(aR[q].z, aR[q].w)); \
            hw[2*q]   = *reinterpret_cast<uint32_t*>(&p0); \
            hw[2*q+1] = *reinterpret_cast<uint32_t*>(&p1); \
        } \
        uint4* a4 = (uint4*)(stg + arow_l * 80 + ahalf * 32); \
        a4[0] = make_uint4(hw[0], hw[1], hw[2], hw[3]); \
        a4[1] = make_uint4(hw[4], hw[5], hw[6], hw[7]); \
    } while (0)

#define CPA_B(c, s) do { \
        uint32_t bdst = sb + (s) * G1_STAGE + 10240; \
        _Pragma("unroll") \
        for (int q = 0; q < 2; q++) { \
            int u = tid + q * 256; \
            int row = u >> 2, j = u & 3; \
            cpasync16(bdst + row * 80 + j * 16, \
                      g_wh + (size_t)row * IN_F + (c) * 32 + j * 8); \
        } \
        asm volatile("cp.async.commit_group;"); \
    } while (0)

    float acc[2][8][4];
#pragma unroll
    for (int m = 0; m < 2; m++)
#pragma unroll
        for (int n = 0; n < 8; n++)
#pragma unroll
            for (int q = 0; q < 4; q++) acc[m][n][q] = 0.f;

    LDG_A(0);
    STS_A(0);
    CPA_B(0, 0);
    LDG_A(1);
    asm volatile("cp.async.wait_group 0;");
    __syncthreads();

    // ldmatrix lane addressing
    const int a_row  = wm * 32 + (lane & 15);
    const int a_koff = (lane >> 4) * 8;
    const int b_n    = wn * 64 + ((lane >> 4) & 1) * 8 + (lane & 7);
    const int b_koff = ((lane >> 3) & 1) * 8;

    for (int c = 0; c < 16; c++) {
        const int s = c & 1;
        uint32_t abase = sb + s * G1_STAGE;
        uint32_t bbase = abase + 10240;

#pragma unroll
        for (int ks = 0; ks < 2; ks++) {
            uint32_t ah[2][4];
#pragma unroll
            for (int m = 0; m < 2; m++) {
                uint32_t ad = abase + (uint32_t)((a_row + m * 16) * 80 + (a_koff + ks * 16) * 2);
                ldsm_x4(ah[m], ad);
            }
#pragma unroll
            for (int g = 0; g < 4; g++) {
                uint32_t bd = bbase + (uint32_t)((b_n + g * 16) * 80 + (b_koff + ks * 16) * 2);
                uint32_t rh[4];
                ldsm_x4(rh, bd);
#pragma unroll
                for (int m = 0; m < 2; m++) {
                    mma16816(acc[m][2*g],   ah[m], rh);
                    mma16816(acc[m][2*g+1], ah[m], rh + 2);
                }
            }
        }

        if (c < 15) {
            STS_A(s ^ 1);
            CPA_B(c + 1, s ^ 1);
            if (c < 14) LDG_A(c + 2);
            asm volatile("cp.async.wait_group 0;");
            __syncthreads();
        }
    }

    // epilogue -> fp16 h1
    const int gid = lane >> 2, tig = lane & 3;
#pragma unroll
    for (int m = 0; m < 2; m++) {
        int r0 = bm + wm * 32 + m * 16 + gid;
#pragma unroll
        for (int n = 0; n < 8; n++) {
            int col = wn * 64 + n * 8 + tig * 2;
            if (r0 < N_NODES) {
                __half2 o = __floats2half2_rn(acc[m][n][0], acc[m][n][1]);
                *(__half2*)&g_h1h[(size_t)r0 * HID + col] = o;
            }
            if (r0 + 8 < N_NODES) {
                __half2 o = __floats2half2_rn(acc[m][n][2], acc[m][n][3]);
                *(__half2*)&g_h1h[(size_t)(r0 + 8) * HID + col] = o;
            }
        }
    }
#undef LDG_A
#undef STS_A
#undef CPA_B
}

// ---------------- SpMM layer 1 (fp16 gather, fp32 acc, 4-way MLP) ------------
__global__ void k_spmm1(const float* __restrict__ b1) {
    int warp = (blockIdx.x * blockDim.x + threadIdx.x) >> 5;
    int lane = threadIdx.x & 31;
    if (warp >= N_NODES) return;
    int row   = warp;
    int start = g_rowstart[row];
    int cnt   = g_cnt[row];

    const uint2* H = reinterpret_cast<const uint2*>(g_h1h);
    const int* cp = g_col + start;
    float4 acc = make_float4(0.f, 0.f, 0.f, 0.f);

    int i = 0;
    for (; i + 4 <= cnt; i += 4) {
        int s0 = cp[i], s1 = cp[i + 1], s2 = cp[i + 2], s3 = cp[i + 3];
        float w0 = g_dinv[s0], w1 = g_dinv[s1], w2 = g_dinv[s2], w3 = g_dinv[s3];
        uint2 v0 = H[(size_t)s0 * 32 + lane];
        uint2 v1 = H[(size_t)s1 * 32 + lane];
        uint2 v2 = H[(size_t)s2 * 32 + lane];
        uint2 v3 = H[(size_t)s3 * 32 + lane];
#define ACCUM(vv, ww) do { \
            float2 f0 = __half22float2(*(__half2*)&(vv).x); \
            float2 f1 = __half22float2(*(__half2*)&(vv).y); \
            acc.x = fmaf((ww), f0.x, acc.x); \
            acc.y = fmaf((ww), f0.y, acc.y); \
            acc.z = fmaf((ww), f1.x, acc.z); \
            acc.w = fmaf((ww), f1.y, acc.w); \
        } while (0)
        ACCUM(v0, w0); ACCUM(v1, w1); ACCUM(v2, w2); ACCUM(v3, w3);
    }
    if (i + 2 <= cnt) {
        int s0 = cp[i], s1 = cp[i + 1];
        float w0 = g_dinv[s0], w1 = g_dinv[s1];
        uint2 v0 = H[(size_t)s0 * 32 + lane];
        uint2 v1 = H[(size_t)s1 * 32 + lane];
        ACCUM(v0, w0); ACCUM(v1, w1);
        i += 2;
    }
    if (i < cnt) {
        int s = cp[i];
        float w = g_dinv[s];
        uint2 v = H[(size_t)s * 32 + lane];
        ACCUM(v, w);
    }
#undef ACCUM

    float d  = g_dinv[row];
    float dd = d * d;
    uint2 hv = H[(size_t)row * 32 + lane];
    float2 s0 = __half22float2(*(__half2*)&hv.x);
    float2 s1 = __half22float2(*(__half2*)&hv.y);
    float4 bb = reinterpret_cast<const float4*>(b1)[lane];
    float4 r;
    r.x = fmaxf(fmaf(d, acc.x, dd * s0.x) + bb.x, 0.f);
    r.y = fmaxf(fmaf(d, acc.y, dd * s0.y) + bb.y, 0.f);
    r.z = fmaxf(fmaf(d, acc.z, dd * s1.x) + bb.z, 0.f);
    r.w = fmaxf(fmaf(d, acc.w, dd * s1.y) + bb.w, 0.f);
    reinterpret_cast<float4*>(g_a1)[(size_t)row * 32 + lane] = r;
}

// ---------------- GEMM2: h2[N,32] = a1[N,128] @ W2[128,32] -------------------
__global__ __launch_bounds__(256) void k_gemm2(const float* __restrict__ W2) {
    __shared__ float As[32 * 132];
    __shared__ float Ws[128 * 32];

    int t    = threadIdx.x;
    int row0 = blockIdx.x * 32;

#pragma unroll
    for (int q = 0; q < 4; q++) {
        int f4 = t + 256 * q;
        *reinterpret_cast<float4*>(&Ws[f4 * 4]) =
            *reinterpret_cast<const float4*>(&W2[f4 * 4]);
        int r  = f4 >> 5;
        int c4 = f4 & 31;
        float4 av = *reinterpret_cast<const float4*>(
            &g_a1[(size_t)(row0 + r) * HID + c4 * 4]);
        *reinterpret_cast<float4*>(&As[r * 132 + c4 * 4]) = av;
    }
    __syncthreads();

    int r  = t >> 3;
    int cg = t & 7;
    float4 acc = make_float4(0.f, 0.f, 0.f, 0.f);
#pragma unroll 4
    for (int k = 0; k < HID; k += 4) {
        float4 a4 = *reinterpret_cast<const float4*>(&As[r * 132 + k]);
        float am[4] = {a4.x, a4.y, a4.z, a4.w};
#pragma unroll
        for (int kk = 0; kk < 4; kk++) {
            float4 w = *reinterpret_cast<const float4*>(&Ws[(k + kk) * 32 + cg * 4]);
            acc.x = fmaf(am[kk], w.x, acc.x);
            acc.y = fmaf(am[kk], w.y, acc.y);
            acc.z = fmaf(am[kk], w.z, acc.z);
            acc.w = fmaf(am[kk], w.w, acc.w);
        }
    }
    __half2 o0 = __floats2half2_rn(acc.x, acc.y);
    __half2 o1 = __floats2half2_rn(acc.z, acc.w);
    uint2 ov = make_uint2(*(uint32_t*)&o0, *(uint32_t*)&o1);
    *reinterpret_cast<uint2*>(&g_h2h[(size_t)(row0 + r) * NCLS + cg * 4]) = ov;
}

// ---------------- SpMM layer 2 (fp16 gather, 4-way MLP) -----------------------
__global__ void k_spmm2(const float* __restrict__ b2, float* __restrict__ out) {
    int warp = (blockIdx.x * blockDim.x + threadIdx.x) >> 5;
    int lane = threadIdx.x & 31;
    if (warp >= N_NODES) return;
    int row   = warp;
    int start = g_rowstart[row];
    int cnt   = g_cnt[row];
    const int* cp = g_col + start;

    float acc = 0.f;
    int i = 0;
    for (; i + 4 <= cnt; i += 4) {
        int s0 = cp[i], s1 = cp[i + 1], s2 = cp[i + 2], s3 = cp[i + 3];
        float w0 = g_dinv[s0], w1 = g_dinv[s1], w2 = g_dinv[s2], w3 = g_dinv[s3];
        float v0 = __half2float(g_h2h[(size_t)s0 * NCLS + lane]);
        float v1 = __half2float(g_h2h[(size_t)s1 * NCLS + lane]);
        float v2 = __half2float(g_h2h[(size_t)s2 * NCLS + lane]);
        float v3 = __half2float(g_h2h[(size_t)s3 * NCLS + lane]);
        acc = fmaf(w0, v0, acc);
        acc = fmaf(w1, v1, acc);
        acc = fmaf(w2, v2, acc);
        acc = fmaf(w3, v3, acc);
    }
    for (; i < cnt; i++) {
        int s = cp[i];
        acc = fmaf(g_dinv[s], __half2float(g_h2h[(size_t)s * NCLS + lane]), acc);
    }
    float d = g_dinv[row];
    float self = __half2float(g_h2h[(size_t)row * NCLS + lane]);
    out[(size_t)row * NCLS + lane] = fmaf(d, acc, d * d * self) + b2[lane];
}

// ---------------- launch ------------------------------------------------------
extern "C" void kernel_launch(void* const* d_in, const int* in_sizes, int n_in,
                              void* d_out, int out_size) {
    const float* x  = (const float*)d_in[0];
    const int*   ei = (const int*)d_in[1];
    const float* W1 = (const float*)d_in[2];
    const float* b1 = (const float*)d_in[3];
    const float* W2 = (const float*)d_in[4];
    const float* b2 = (const float*)d_in[5];
    float* out = (float*)d_out;

    int E = in_sizes[1] / 2;
    const int* src = ei;
    const int* dst = ei + E;

    int nScanBlocks = (N_NODES + 1023) / 1024;   // 98

    static cudaStream_t s2 = nullptr;
    static cudaEvent_t evFork = nullptr, evJoin = nullptr;
    static bool init_done = false;
    if (!init_done) {
        cudaFuncSetAttribute(k_gemm1_mma,
                             cudaFuncAttributeMaxDynamicSharedMemorySize,
                             G1_SMEM);
        cudaStreamCreateWithFlags(&s2, cudaStreamNonBlocking);
        cudaEventCreateWithFlags(&evFork, cudaEventDisableTiming);
        cudaEventCreateWithFlags(&evJoin, cudaEventDisableTiming);
        init_done = true;
    }

    // fork: CSR build on s2, GEMM path on the main (captured) stream
    cudaEventRecord(evFork, 0);
    cudaStreamWaitEvent(s2, evFork, 0);

    k_zero_cnt<<<(N_NODES + 255) / 256, 256, 0, s2>>>();
    k_hist<<<(E + 255) / 256, 256, 0, s2>>>(dst, E);
    k_scan1<<<nScanBlocks, 256, 0, s2>>>();
    k_scan2<<<1, 128, 0, s2>>>(nScanBlocks);
    k_scan3<<<(N_NODES + 255) / 256, 256, 0, s2>>>();
    k_fill<<<(E + 255) / 256, 256, 0, s2>>>(src, dst, E);
    cudaEventRecord(evJoin, s2);

    k_prepw<<<64, 256>>>(W1);
    k_gemm1_mma<<<(N_NODES + 127) / 128, 256, G1_SMEM>>>(x);

    // join
    cudaStreamWaitEvent(0, evJoin, 0);

    k_spmm1<<<(N_NODES + 7) / 8, 256>>>(b1);
    k_gemm2<<<N_NODES / 32, 256>>>(W2);
    k_spmm2<<<(N_NODES + 7) / 8, 256>>>(b2, out);
}

// round 9
// speedup vs baseline: 2.1234x; 1.0144x over previous
#include <cuda_runtime.h>
#include <cuda_fp16.h>
#include <cstdint>

#define N_NODES 100000
#define E_MAX   1600000
#define IN_F    512
#define HID     128
#define NCLS    32

// ---------------- scratch (device globals; no allocation allowed) ------------
__device__ int    g_cnt[N_NODES];
__device__ int    g_rowstart[N_NODES];
__device__ int    g_cursor[N_NODES];
__device__ float  g_dinv[N_NODES];
__device__ int    g_col[E_MAX];
__device__ __half g_h1h[(size_t)N_NODES * HID];   // x @ W1 (fp16)
__device__ __half g_h2h[(size_t)N_NODES * NCLS];  // gcn1(x) @ W2 (fp16)
__device__ int    g_blocksums[128];
// W1 transposed to [N=128][K=512], fp16
__device__ __half g_wh[HID * IN_F];

__device__ __forceinline__ uint32_t smem_u32(const void* p) {
    uint32_t a;
    asm("{ .reg .u64 t; cvta.to.shared.u64 t, %1; cvt.u32.u64 %0, t; }"
        : "=r"(a) : "l"(p));
    return a;
}

__device__ __forceinline__ void ldsm_x4(uint32_t* r, uint32_t addr) {
    asm volatile("ldmatrix.sync.aligned.m8n8.x4.shared.b16 {%0,%1,%2,%3}, [%4];"
                 : "=r"(r[0]), "=r"(r[1]), "=r"(r[2]), "=r"(r[3]) : "r"(addr));
}

__device__ __forceinline__ void mma16816(float* d, const uint32_t* a, const uint32_t* b) {
    asm volatile(
        "mma.sync.aligned.m16n8k16.row.col.f32.f16.f16.f32 "
        "{%0,%1,%2,%3}, {%4,%5,%6,%7}, {%8,%9}, {%0,%1,%2,%3};"
        : "+f"(d[0]), "+f"(d[1]), "+f"(d[2]), "+f"(d[3])
        : "r"(a[0]), "r"(a[1]), "r"(a[2]), "r"(a[3]), "r"(b[0]), "r"(b[1]));
}

__device__ __forceinline__ void cpasync16(uint32_t dst, const void* src) {
    size_t g = __cvta_generic_to_global(src);
    asm volatile("cp.async.cg.shared.global [%0], [%1], 16;" :: "r"(dst), "l"(g));
}

// ---------------- small helpers ------------------------------------------
__global__ void k_zero_cnt() {
    int i = blockIdx.x * blockDim.x + threadIdx.x;
    if (i < N_NODES) g_cnt[i] = 0;
}

__global__ void k_hist(const int* __restrict__ dst, int E) {
    int e = blockIdx.x * blockDim.x + threadIdx.x;
    if (e < E) atomicAdd(&g_cnt[dst[e]], 1);
}

// W1 [512][128] -> transpose + fp16 -> g_wh [128][512]
__global__ void k_prepw(const float* __restrict__ W1) {
    __shared__ float sh[32][33];
    int bi = blockIdx.x & 15;        // k tile
    int bj = blockIdx.x >> 4;        // n tile
    int k0 = bi * 32, n0 = bj * 32;
    int t = threadIdx.x;
    int i = t >> 5, j = t & 31;
#pragma unroll
    for (int r = 0; r < 4; r++) {
        int kk = i + r * 8;
        sh[kk][j] = W1[(size_t)(k0 + kk) * HID + n0 + j];
    }
    __syncthreads();
#pragma unroll
    for (int r = 0; r < 4; r++) {
        int nn = i + r * 8;
        g_wh[(size_t)(n0 + nn) * IN_F + k0 + j] = __float2half_rn(sh[j][nn]);
    }
}

__global__ void k_scan1() {
    __shared__ int sh[256];
    int b = blockIdx.x, t = threadIdx.x;
    int base = b * 1024 + t * 4;
    int v[4];
    int local = 0;
#pragma unroll
    for (int q = 0; q < 4; q++) {
        int i = base + q;
        v[q] = (i < N_NODES) ? g_cnt[i] : 0;
        local += v[q];
    }
    sh[t] = local;
    __syncthreads();
#pragma unroll
    for (int off = 1; off < 256; off <<= 1) {
        int add = (t >= off) ? sh[t - off] : 0;
        __syncthreads();
        sh[t] += add;
        __syncthreads();
    }
    int run = sh[t] - local;
    if (t == 255) g_blocksums[b] = sh[255];
#pragma unroll
    for (int q = 0; q < 4; q++) {
        int i = base + q;
        if (i < N_NODES) g_rowstart[i] = run;
        run += v[q];
    }
}

__global__ void k_scan2(int nblk) {
    __shared__ int sh[128];
    int t = threadIdx.x;
    int v = (t < nblk) ? g_blocksums[t] : 0;
    sh[t] = v;
    __syncthreads();
#pragma unroll
    for (int off = 1; off < 128; off <<= 1) {
        int add = (t >= off) ? sh[t - off] : 0;
        __syncthreads();
        sh[t] += add;
        __syncthreads();
    }
    if (t < nblk) g_blocksums[t] = sh[t] - v;
}

__global__ void k_scan3() {
    int i = blockIdx.x * blockDim.x + threadIdx.x;
    if (i >= N_NODES) return;
    int rs = g_rowstart[i] + g_blocksums[i >> 10];
    g_rowstart[i] = rs;
    g_cursor[i]   = rs;
    g_dinv[i]     = rsqrtf((float)(g_cnt[i] + 1));
}

__global__ void k_fill(const int* __restrict__ src, const int* __restrict__ dst, int E) {
    int e = blockIdx.x * blockDim.x + threadIdx.x;
    if (e >= E) return;
    int d = dst[e];
    int p = atomicAdd(&g_cursor[d], 1);
    g_col[p] = src[e];
}

// ---------------- GEMM1: h1 = X @ W1, single-pass fp16 mma -------------------
// BM=128, BN=128, BK=32, double-buffered, 2 CTAs/SM.
// Warps 4m x 2n; per warp mt=2, nt=8 (64 acc regs/thread).
#define G1_STAGE   20480
#define G1_SMEM    (2 * G1_STAGE)

__global__ __launch_bounds__(256, 2) void k_gemm1_mma(const float* __restrict__ X) {
    extern __shared__ char smem[];
    uint32_t sb = smem_u32(smem);

    const int tid  = threadIdx.x;
    const int wid  = tid >> 5;
    const int lane = tid & 31;
    const int bm   = blockIdx.x * 128;
    const int wm   = wid & 3;
    const int wn   = wid >> 2;

    const int arow_l = tid >> 1;
    const int ahalf  = tid & 1;
    int arow_g = bm + arow_l;
    if (arow_g >= N_NODES) arow_g = N_NODES - 1;
    const float* aptr = X + (size_t)arow_g * IN_F + ahalf * 16;

    float4 aR[4];

#define LDG_A(c) do { \
        const float4* p4 = (const float4*)(aptr + (c) * 32); \
        _Pragma("unroll") \
        for (int q = 0; q < 4; q++) aR[q] = p4[q]; \
    } while (0)

#define STS_A(s) do { \
        char* stg = smem + (s) * G1_STAGE; \
        uint32_t hw[8]; \
        _Pragma("unroll") \
        for (int q = 0; q < 4; q++) { \
            __half2 p0 = __float22half2_rn(make_float2(aR[q].x, aR[q].y)); \
            __half2 p1 = __float22half2_rn(make_float2(aR[q].z, aR[q].w)); \
            hw[2*q]   = *reinterpret_cast<uint32_t*>(&p0); \
            hw[2*q+1] = *reinterpret_cast<uint32_t*>(&p1); \
        } \
        uint4* a4 = (uint4*)(stg + arow_l * 80 + ahalf * 32); \
        a4[0] = make_uint4(hw[0], hw[1], hw[2], hw[3]); \
        a4[1] = make_uint4(hw[4], hw[5], hw[6], hw[7]); \
    } while (0)

#define CPA_B(c, s) do { \
        uint32_t bdst = sb + (s) * G1_STAGE + 10240; \
        _Pragma("unroll") \
        for (int q = 0; q < 2; q++) { \
            int u = tid + q * 256; \
            int row = u >> 2, j = u & 3; \
            cpasync16(bdst + row * 80 + j * 16, \
                      g_wh + (size_t)row * IN_F + (c) * 32 + j * 8); \
        } \
        asm volatile("cp.async.commit_group;"); \
    } while (0)

    float acc[2][8][4];
#pragma unroll
    for (int m = 0; m < 2; m++)
#pragma unroll
        for (int n = 0; n < 8; n++)
#pragma unroll
            for (int q = 0; q < 4; q++) acc[m][n][q] = 0.f;

    LDG_A(0);
    STS_A(0);
    CPA_B(0, 0);
    LDG_A(1);
    asm volatile("cp.async.wait_group 0;");
    __syncthreads();

    const int a_row  = wm * 32 + (lane & 15);
    const int a_koff = (lane >> 4) * 8;
    const int b_n    = wn * 64 + ((lane >> 4) & 1) * 8 + (lane & 7);
    const int b_koff = ((lane >> 3) & 1) * 8;

    for (int c = 0; c < 16; c++) {
        const int s = c & 1;
        uint32_t abase = sb + s * G1_STAGE;
        uint32_t bbase = abase + 10240;

#pragma unroll
        for (int ks = 0; ks < 2; ks++) {
            uint32_t ah[2][4];
#pragma unroll
            for (int m = 0; m < 2; m++) {
                uint32_t ad = abase + (uint32_t)((a_row + m * 16) * 80 + (a_koff + ks * 16) * 2);
                ldsm_x4(ah[m], ad);
            }
#pragma unroll
            for (int g = 0; g < 4; g++) {
                uint32_t bd = bbase + (uint32_t)((b_n + g * 16) * 80 + (b_koff + ks * 16) * 2);
                uint32_t rh[4];
                ldsm_x4(rh, bd);
#pragma unroll
                for (int m = 0; m < 2; m++) {
                    mma16816(acc[m][2*g],   ah[m], rh);
                    mma16816(acc[m][2*g+1], ah[m], rh + 2);
                }
            }
        }

        if (c < 15) {
            STS_A(s ^ 1);
            CPA_B(c + 1, s ^ 1);
            if (c < 14) LDG_A(c + 2);
            asm volatile("cp.async.wait_group 0;");
            __syncthreads();
        }
    }

    const int gid = lane >> 2, tig = lane & 3;
#pragma unroll
    for (int m = 0; m < 2; m++) {
        int r0 = bm + wm * 32 + m * 16 + gid;
#pragma unroll
        for (int n = 0; n < 8; n++) {
            int col = wn * 64 + n * 8 + tig * 2;
            if (r0 < N_NODES) {
                __half2 o = __floats2half2_rn(acc[m][n][0], acc[m][n][1]);
                *(__half2*)&g_h1h[(size_t)r0 * HID + col] = o;
            }
            if (r0 + 8 < N_NODES) {
                __half2 o = __floats2half2_rn(acc[m][n][2], acc[m][n][3]);
                *(__half2*)&g_h1h[(size_t)(r0 + 8) * HID + col] = o;
            }
        }
    }
#undef LDG_A
#undef STS_A
#undef CPA_B
}

// ---------------- Fused SpMM1 + GEMM2 -----------------------------------------
// Per warp: aggregate h1 row (fp16 gather, fp32 acc) -> relu(+b1) -> a1 row in
// shared -> h2[row][lane] = sum_k a1[k] * W2[k][lane]  (one class per lane).
// a1 never touches global memory; gemm2 kernel eliminated.
__global__ __launch_bounds__(256) void k_spmm1g2(const float* __restrict__ b1,
                                                 const float* __restrict__ W2) {
    __shared__ float W2s[HID * NCLS];      // 16 KB
    __shared__ float a1s[8][HID];          // 4 KB (per-warp row buffer)

    int t = threadIdx.x;
    // load W2 once per block: 4096 floats = 4 float4/thread
#pragma unroll
    for (int q = 0; q < 4; q++) {
        int f4 = t + 256 * q;
        *reinterpret_cast<float4*>(&W2s[f4 * 4]) =
            *reinterpret_cast<const float4*>(&W2[f4 * 4]);
    }
    __syncthreads();

    int warp = (blockIdx.x * blockDim.x + t) >> 5;
    int wi   = (t >> 5);        // warp in block
    int lane = t & 31;
    if (warp >= N_NODES) return;
    int row   = warp;
    int start = g_rowstart[row];
    int cnt   = g_cnt[row];

    const uint2* H = reinterpret_cast<const uint2*>(g_h1h);
    const int* cp = g_col + start;
    float4 acc = make_float4(0.f, 0.f, 0.f, 0.f);

    int i = 0;
    for (; i + 4 <= cnt; i += 4) {
        int s0 = cp[i], s1 = cp[i + 1], s2 = cp[i + 2], s3 = cp[i + 3];
        float w0 = g_dinv[s0], w1 = g_dinv[s1], w2 = g_dinv[s2], w3 = g_dinv[s3];
        uint2 v0 = H[(size_t)s0 * 32 + lane];
        uint2 v1 = H[(size_t)s1 * 32 + lane];
        uint2 v2 = H[(size_t)s2 * 32 + lane];
        uint2 v3 = H[(size_t)s3 * 32 + lane];
#define ACCUM(vv, ww) do { \
            float2 f0 = __half22float2(*(__half2*)&(vv).x); \
            float2 f1 = __half22float2(*(__half2*)&(vv).y); \
            acc.x = fmaf((ww), f0.x, acc.x); \
            acc.y = fmaf((ww), f0.y, acc.y); \
            acc.z = fmaf((ww), f1.x, acc.z); \
            acc.w = fmaf((ww), f1.y, acc.w); \
        } while (0)
        ACCUM(v0, w0); ACCUM(v1, w1); ACCUM(v2, w2); ACCUM(v3, w3);
    }
    if (i + 2 <= cnt) {
        int s0 = cp[i], s1 = cp[i + 1];
        float w0 = g_dinv[s0], w1 = g_dinv[s1];
        uint2 v0 = H[(size_t)s0 * 32 + lane];
        uint2 v1 = H[(size_t)s1 * 32 + lane];
        ACCUM(v0, w0); ACCUM(v1, w1);
        i += 2;
    }
    if (i < cnt) {
        int s = cp[i];
        float w = g_dinv[s];
        uint2 v = H[(size_t)s * 32 + lane];
        ACCUM(v, w);
    }
#undef ACCUM

    float d  = g_dinv[row];
    float dd = d * d;
    uint2 hv = H[(size_t)row * 32 + lane];
    float2 s0 = __half22float2(*(__half2*)&hv.x);
    float2 s1 = __half22float2(*(__half2*)&hv.y);
    float4 bb = reinterpret_cast<const float4*>(b1)[lane];
    float4 r;
    r.x = fmaxf(fmaf(d, acc.x, dd * s0.x) + bb.x, 0.f);
    r.y = fmaxf(fmaf(d, acc.y, dd * s0.y) + bb.y, 0.f);
    r.z = fmaxf(fmaf(d, acc.z, dd * s1.x) + bb.z, 0.f);
    r.w = fmaxf(fmaf(d, acc.w, dd * s1.y) + bb.w, 0.f);

    // stage a1 row in shared (per-warp buffer)
    *reinterpret_cast<float4*>(&a1s[wi][lane * 4]) = r;
    __syncwarp();

    // mat-vec: each lane computes one class
    float o = 0.f;
#pragma unroll 8
    for (int k = 0; k < HID; k += 4) {
        float4 a4 = *reinterpret_cast<const float4*>(&a1s[wi][k]);   // broadcast
        o = fmaf(a4.x, W2s[(k + 0) * NCLS + lane], o);
        o = fmaf(a4.y, W2s[(k + 1) * NCLS + lane], o);
        o = fmaf(a4.z, W2s[(k + 2) * NCLS + lane], o);
        o = fmaf(a4.w, W2s[(k + 3) * NCLS + lane], o);
    }
    g_h2h[(size_t)row * NCLS + lane] = __float2half_rn(o);
}

// ---------------- SpMM layer 2 (fp16 gather, 4-way MLP) -----------------------
__global__ void k_spmm2(const float* __restrict__ b2, float* __restrict__ out) {
    int warp = (blockIdx.x * blockDim.x + threadIdx.x) >> 5;
    int lane = threadIdx.x & 31;
    if (warp >= N_NODES) return;
    int row   = warp;
    int start = g_rowstart[row];
    int cnt   = g_cnt[row];
    const int* cp = g_col + start;

    float acc = 0.f;
    int i = 0;
    for (; i + 4 <= cnt; i += 4) {
        int s0 = cp[i], s1 = cp[i + 1], s2 = cp[i + 2], s3 = cp[i + 3];
        float w0 = g_dinv[s0], w1 = g_dinv[s1], w2 = g_dinv[s2], w3 = g_dinv[s3];
        float v0 = __half2float(g_h2h[(size_t)s0 * NCLS + lane]);
        float v1 = __half2float(g_h2h[(size_t)s1 * NCLS + lane]);
        float v2 = __half2float(g_h2h[(size_t)s2 * NCLS + lane]);
        float v3 = __half2float(g_h2h[(size_t)s3 * NCLS + lane]);
        acc = fmaf(w0, v0, acc);
        acc = fmaf(w1, v1, acc);
        acc = fmaf(w2, v2, acc);
        acc = fmaf(w3, v3, acc);
    }
    for (; i < cnt; i++) {
        int s = cp[i];
        acc = fmaf(g_dinv[s], __half2float(g_h2h[(size_t)s * NCLS + lane]), acc);
    }
    float d = g_dinv[row];
    float self = __half2float(g_h2h[(size_t)row * NCLS + lane]);
    out[(size_t)row * NCLS + lane] = fmaf(d, acc, d * d * self) + b2[lane];
}

// ---------------- launch ------------------------------------------------------
extern "C" void kernel_launch(void* const* d_in, const int* in_sizes, int n_in,
                              void* d_out, int out_size) {
    const float* x  = (const float*)d_in[0];
    const int*   ei = (const int*)d_in[1];
    const float* W1 = (const float*)d_in[2];
    const float* b1 = (const float*)d_in[3];
    const float* W2 = (const float*)d_in[4];
    const float* b2 = (const float*)d_in[5];
    float* out = (float*)d_out;

    int E = in_sizes[1] / 2;
    const int* src = ei;
    const int* dst = ei + E;

    int nScanBlocks = (N_NODES + 1023) / 1024;   // 98

    static cudaStream_t s2 = nullptr;
    static cudaEvent_t evFork = nullptr, evJoin = nullptr;
    static bool init_done = false;
    if (!init_done) {
        cudaFuncSetAttribute(k_gemm1_mma,
                             cudaFuncAttributeMaxDynamicSharedMemorySize,
                             G1_SMEM);
        cudaStreamCreateWithFlags(&s2, cudaStreamNonBlocking);
        cudaEventCreateWithFlags(&evFork, cudaEventDisableTiming);
        cudaEventCreateWithFlags(&evJoin, cudaEventDisableTiming);
        init_done = true;
    }

    // fork: CSR build on s2, GEMM path on the main (captured) stream
    cudaEventRecord(evFork, 0);
    cudaStreamWaitEvent(s2, evFork, 0);

    k_zero_cnt<<<(N_NODES + 255) / 256, 256, 0, s2>>>();
    k_hist<<<(E + 255) / 256, 256, 0, s2>>>(dst, E);
    k_scan1<<<nScanBlocks, 256, 0, s2>>>();
    k_scan2<<<1, 128, 0, s2>>>(nScanBlocks);
    k_scan3<<<(N_NODES + 255) / 256, 256, 0, s2>>>();
    k_fill<<<(E + 255) / 256, 256, 0, s2>>>(src, dst, E);
    cudaEventRecord(evJoin, s2);

    k_prepw<<<64, 256>>>(W1);
    k_gemm1_mma<<<(N_NODES + 127) / 128, 256, G1_SMEM>>>(x);

    // join
    cudaStreamWaitEvent(0, evJoin, 0);

    k_spmm1g2<<<(N_NODES + 7) / 8, 256>>>(b1, W2);
    k_spmm2<<<(N_NODES + 7) / 8, 256>>>(b2, out);
}